// round 1
// baseline (speedup 1.0000x reference)
#include <cuda_runtime.h>

#define B_   256
#define LD_  64
#define NO_  10240
#define LO_  32
#define NM_  81920
#define LM_  16
#define EO_  81920
#define EM_  327680
#define E_   128
#define HID_ 256
#define H_   8
#define Dh_  16

// ---------------- scratch (device globals; no allocation allowed) ----------------
__device__ float g_hn[B_ * E_];
__device__ float g_stmt[NO_ * E_];
__device__ float g_mini[NM_ * E_];
__device__ float g_q[NM_ * E_];
__device__ float g_k[NM_ * E_];
__device__ float g_v[NM_ * E_];
__device__ float g_hidden[NM_ * E_];     // skip output, then += attention agg
__device__ float g_score[EM_ * H_];      // scores, then exp() in-place
__device__ float g_smax[NM_ * H_];
__device__ float g_ssum[NM_ * H_];
__device__ float g_minifn[NO_ * E_];
__device__ int   g_degcnt[NO_];
__device__ float g_dinv[NO_];
__device__ float g_xw1[NO_ * HID_];
__device__ float g_gc1[NO_ * HID_];
__device__ float g_xw2[NO_ * E_];
__device__ float g_fs[NO_ * E_];
__device__ float g_fn[B_ * E_];

// ---------------- helpers ----------------
__device__ __forceinline__ void atomicMaxFloat(float* addr, float value) {
    if (value >= 0.f)
        atomicMax((int*)addr, __float_as_int(value));
    else
        atomicMin((unsigned int*)addr, __float_as_uint(value));
}

// ---------------- init ----------------
__global__ void init_kernel() {
    int i = blockIdx.x * blockDim.x + threadIdx.x;
    if (i < NM_ * H_) { g_smax[i] = -1e30f; g_ssum[i] = 0.f; }
    if (i < NO_) g_degcnt[i] = 1;  // self loop
}

// ---------------- masked mean embedding pool ----------------
// one node per block, 128 threads (one per embedding dim)
__global__ void masked_mean_kernel(const int* __restrict__ tok,
                                   const float* __restrict__ table,
                                   float* __restrict__ out, int L) {
    __shared__ int ts[64];
    int n = blockIdx.x;
    int d = threadIdx.x;
    if (d < L) ts[d] = tok[n * L + d];
    __syncthreads();
    float acc = 0.f;
    int cnt = 0;
    for (int j = 0; j < L; j++) {
        int t = ts[j];
        if (t != 0) { acc += table[t * E_ + d]; cnt++; }
    }
    out[(size_t)n * E_ + d] = acc / (float)(cnt > 1 ? cnt : 1);
}

// ---------------- SGEMM: C[N,M] = (reluA? relu(A) : A)[N,K] @ W[K,M] (+ bias) ----
// 64x64 tile, 256 threads, 4x4 microtile. All dims divisible by 64/16 here.
__global__ void sgemm64(const float* __restrict__ A, const float* __restrict__ W,
                        const float* __restrict__ bias, float* __restrict__ C,
                        int N, int K, int M, int reluA) {
    __shared__ float As[16][64];
    __shared__ float Bs[16][64];
    int tid = threadIdx.x;
    int tx = tid & 15, ty = tid >> 4;
    int row0 = blockIdx.x * 64, col0 = blockIdx.y * 64;
    float acc[4][4] = {};
    for (int kt = 0; kt < K; kt += 16) {
#pragma unroll
        for (int r = 0; r < 4; r++) {
            int i = tid + r * 256;
            int ar = i >> 4, ak = i & 15;
            float v = A[(size_t)(row0 + ar) * K + kt + ak];
            if (reluA) v = fmaxf(v, 0.f);
            As[ak][ar] = v;
        }
#pragma unroll
        for (int r = 0; r < 4; r++) {
            int i = tid + r * 256;
            int bk = i >> 6, bc = i & 63;
            Bs[bk][bc] = W[(size_t)(kt + bk) * M + col0 + bc];
        }
        __syncthreads();
#pragma unroll
        for (int k = 0; k < 16; k++) {
            float4 a4 = *(const float4*)&As[k][ty * 4];
            float4 b4 = *(const float4*)&Bs[k][tx * 4];
            float a[4] = {a4.x, a4.y, a4.z, a4.w};
            float b[4] = {b4.x, b4.y, b4.z, b4.w};
#pragma unroll
            for (int i2 = 0; i2 < 4; i2++)
#pragma unroll
                for (int j = 0; j < 4; j++) acc[i2][j] += a[i2] * b[j];
        }
        __syncthreads();
    }
#pragma unroll
    for (int i2 = 0; i2 < 4; i2++) {
        int row = row0 + ty * 4 + i2;
#pragma unroll
        for (int j = 0; j < 4; j++) {
            int col = col0 + tx * 4 + j;
            float bv = bias ? bias[col] : 0.f;
            C[(size_t)row * M + col] = acc[i2][j] + bv;
        }
    }
}

// ---------------- transformer conv: edge scores ----------------
// one edge per 128-thread block; 16 lanes per head
__global__ void edge_score_kernel(const int* __restrict__ src, const int* __restrict__ dst) {
    int e = blockIdx.x;
    int d = threadIdx.x;
    int s = src[e], t = dst[e];
    float p = g_q[(size_t)t * E_ + d] * g_k[(size_t)s * E_ + d];
    p += __shfl_down_sync(0xffffffffu, p, 8, 16);
    p += __shfl_down_sync(0xffffffffu, p, 4, 16);
    p += __shfl_down_sync(0xffffffffu, p, 2, 16);
    p += __shfl_down_sync(0xffffffffu, p, 1, 16);
    if ((d & 15) == 0) {
        int h = d >> 4;
        float sc = p * 0.25f;  // 1/sqrt(Dh)
        g_score[(size_t)e * H_ + h] = sc;
        atomicMaxFloat(&g_smax[(size_t)t * H_ + h], sc);
    }
}

__global__ void edge_exp_kernel(const int* __restrict__ dst) {
    int idx = blockIdx.x * blockDim.x + threadIdx.x;
    if (idx >= EM_ * H_) return;
    int e = idx >> 3, h = idx & 7;
    int t = dst[e];
    float ex = expf(g_score[idx] - g_smax[(size_t)t * H_ + h]);
    g_score[idx] = ex;
    atomicAdd(&g_ssum[(size_t)t * H_ + h], ex);
}

__global__ void edge_agg_kernel(const int* __restrict__ src, const int* __restrict__ dst) {
    int e = blockIdx.x;
    int d = threadIdx.x;
    int h = d >> 4;
    int s = src[e], t = dst[e];
    float a = g_score[(size_t)e * H_ + h] / (g_ssum[(size_t)t * H_ + h] + 1e-16f);
    atomicAdd(&g_hidden[(size_t)t * E_ + d], a * g_v[(size_t)s * E_ + d]);
}

// ---------------- global attention over contiguous segments of 8 (mini->NO) ----
// fused with (attn + stmt_emb) * 0.5 ; one warp per output node
__global__ void gattn8_kernel(const float* __restrict__ Wg, const float* __restrict__ bg) {
    int warp = threadIdx.x >> 5;
    int lane = threadIdx.x & 31;
    int n = blockIdx.x * 8 + warp;
    const float4* x4 = (const float4*)g_hidden;
    float4 wg = ((const float4*)Wg)[lane];
    float bgv = bg[0];
    float4 xr[8];
    float g[8];
#pragma unroll
    for (int j = 0; j < 8; j++) {
        float4 xv = x4[(size_t)(n * 8 + j) * 32 + lane];
        xr[j] = xv;
        float p = xv.x * wg.x + xv.y * wg.y + xv.z * wg.z + xv.w * wg.w;
#pragma unroll
        for (int off = 16; off; off >>= 1) p += __shfl_xor_sync(0xffffffffu, p, off);
        g[j] = p + bgv;
    }
    float m = g[0];
#pragma unroll
    for (int j = 1; j < 8; j++) m = fmaxf(m, g[j]);
    float ej[8], s = 0.f;
#pragma unroll
    for (int j = 0; j < 8; j++) { ej[j] = expf(g[j] - m); s += ej[j]; }
    float inv = 1.f / (s + 1e-16f);
    float4 o = {0.f, 0.f, 0.f, 0.f};
#pragma unroll
    for (int j = 0; j < 8; j++) {
        float a = ej[j] * inv;
        o.x += a * xr[j].x; o.y += a * xr[j].y; o.z += a * xr[j].z; o.w += a * xr[j].w;
    }
    float4 st = ((const float4*)g_stmt)[(size_t)n * 32 + lane];
    float4 res = {(o.x + st.x) * 0.5f, (o.y + st.y) * 0.5f,
                  (o.z + st.z) * 0.5f, (o.w + st.w) * 0.5f};
    ((float4*)g_minifn)[(size_t)n * 32 + lane] = res;
}

// ---------------- GCN ----------------
__global__ void deg_kernel(const int* __restrict__ dst) {
    int i = blockIdx.x * blockDim.x + threadIdx.x;
    if (i < EO_) atomicAdd(&g_degcnt[dst[i]], 1);
}
__global__ void dinv_kernel() {
    int i = blockIdx.x * blockDim.x + threadIdx.x;
    if (i < NO_) g_dinv[i] = rsqrtf((float)g_degcnt[i]);
}
// out[n,:] = xw[n,:]*dinv[n]^2 + bias  (self loop term + bias)
__global__ void gcn_init_kernel(const float* __restrict__ xw, const float* __restrict__ bias,
                                float* __restrict__ out, int M) {
    int n = blockIdx.x;
    int m = threadIdx.x;
    float di = g_dinv[n];
    out[(size_t)n * M + m] = xw[(size_t)n * M + m] * di * di + bias[m];
}
__global__ void gcn_edge_kernel(const int* __restrict__ src, const int* __restrict__ dst,
                                const float* __restrict__ xw, float* __restrict__ out, int M) {
    int e = blockIdx.x;
    int m = threadIdx.x;
    int s = src[e], t = dst[e];
    float norm = g_dinv[s] * g_dinv[t];
    atomicAdd(&out[(size_t)t * M + m], norm * xw[(size_t)s * M + m]);
}

// ---------------- global attention over contiguous segments of 40 (NO->B) ----
__global__ void gattn40_kernel(const float* __restrict__ Wg, const float* __restrict__ bg) {
    __shared__ float gate[40];
    __shared__ float alpha[40];
    __shared__ float ms[2];
    int b = blockIdx.x;
    int tid = threadIdx.x;  // 128
    int warp = tid >> 5, lane = tid & 31;
    float4 wg = ((const float4*)Wg)[lane];
    for (int j = warp; j < 40; j += 4) {
        float4 xv = ((const float4*)g_fs)[(size_t)(b * 40 + j) * 32 + lane];
        float p = xv.x * wg.x + xv.y * wg.y + xv.z * wg.z + xv.w * wg.w;
#pragma unroll
        for (int off = 16; off; off >>= 1) p += __shfl_xor_sync(0xffffffffu, p, off);
        if (lane == 0) gate[j] = p + bg[0];
    }
    __syncthreads();
    if (tid == 0) {
        float m = gate[0];
        for (int j = 1; j < 40; j++) m = fmaxf(m, gate[j]);
        float s = 0.f;
        for (int j = 0; j < 40; j++) s += expf(gate[j] - m);
        ms[0] = m; ms[1] = s;
    }
    __syncthreads();
    if (tid < 40) alpha[tid] = expf(gate[tid] - ms[0]) / (ms[1] + 1e-16f);
    __syncthreads();
    float acc = 0.f;
    for (int j = 0; j < 40; j++)
        acc += alpha[j] * g_fs[(size_t)(b * 40 + j) * E_ + tid];
    g_fn[(size_t)b * E_ + tid] = acc;
}

// ---------------- cosine similarity ----------------
__global__ void cos_kernel(float* __restrict__ out) {
    int warp = threadIdx.x >> 5, lane = threadIdx.x & 31;
    int b = blockIdx.x * 8 + warp;
    float4 a4 = ((const float4*)g_fn)[(size_t)b * 32 + lane];
    float4 b4 = ((const float4*)g_hn)[(size_t)b * 32 + lane];
    float dt = a4.x * b4.x + a4.y * b4.y + a4.z * b4.z + a4.w * b4.w;
    float na = a4.x * a4.x + a4.y * a4.y + a4.z * a4.z + a4.w * a4.w;
    float nb = b4.x * b4.x + b4.y * b4.y + b4.z * b4.z + b4.w * b4.w;
#pragma unroll
    for (int off = 16; off; off >>= 1) {
        dt += __shfl_xor_sync(0xffffffffu, dt, off);
        na += __shfl_xor_sync(0xffffffffu, na, off);
        nb += __shfl_xor_sync(0xffffffffu, nb, off);
    }
    if (lane == 0)
        out[b] = dt / (fmaxf(sqrtf(na), 1e-8f) * fmaxf(sqrtf(nb), 1e-8f));
}

// ---------------- launch ----------------
extern "C" void kernel_launch(void* const* d_in, const int* in_sizes, int n_in,
                              void* d_out, int out_size) {
    const int* desc_tokens = (const int*)d_in[0];
    const int* x_tokens    = (const int*)d_in[1];
    const int* mini_tokens = (const int*)d_in[2];
    const int* src         = (const int*)d_in[3];
    const int* dst         = (const int*)d_in[4];
    const int* mini_src    = (const int*)d_in[5];
    const int* mini_dst    = (const int*)d_in[6];
    // d_in[7] mini_batch, d_in[8] node_batch: contiguous segments (i//8, i//40)
    const float* desc_table  = (const float*)d_in[9];
    const float* code_table  = (const float*)d_in[10];
    const float* code_table2 = (const float*)d_in[11];
    const float* Wq = (const float*)d_in[12]; const float* bq = (const float*)d_in[13];
    const float* Wk = (const float*)d_in[14]; const float* bk = (const float*)d_in[15];
    const float* Wv = (const float*)d_in[16]; const float* bv = (const float*)d_in[17];
    const float* Wskip = (const float*)d_in[18]; const float* bskip = (const float*)d_in[19];
    const float* W2 = (const float*)d_in[20]; const float* b2 = (const float*)d_in[21];
    const float* W3 = (const float*)d_in[22]; const float* b3 = (const float*)d_in[23];
    const float* Wg = (const float*)d_in[24]; const float* bg = (const float*)d_in[25];
    float* out = (float*)d_out;

    float *p_mini, *p_q, *p_k, *p_v, *p_hidden, *p_hn, *p_stmt, *p_minifn;
    float *p_xw1, *p_gc1, *p_xw2, *p_fs;
    cudaGetSymbolAddress((void**)&p_mini, g_mini);
    cudaGetSymbolAddress((void**)&p_q, g_q);
    cudaGetSymbolAddress((void**)&p_k, g_k);
    cudaGetSymbolAddress((void**)&p_v, g_v);
    cudaGetSymbolAddress((void**)&p_hidden, g_hidden);
    cudaGetSymbolAddress((void**)&p_hn, g_hn);
    cudaGetSymbolAddress((void**)&p_stmt, g_stmt);
    cudaGetSymbolAddress((void**)&p_minifn, g_minifn);
    cudaGetSymbolAddress((void**)&p_xw1, g_xw1);
    cudaGetSymbolAddress((void**)&p_gc1, g_gc1);
    cudaGetSymbolAddress((void**)&p_xw2, g_xw2);
    cudaGetSymbolAddress((void**)&p_fs, g_fs);

    // init scratch
    init_kernel<<<(NM_ * H_ + 255) / 256, 256>>>();

    // embeddings (masked mean pools)
    masked_mean_kernel<<<B_, E_>>>(desc_tokens, desc_table, p_hn, LD_);
    masked_mean_kernel<<<NO_, E_>>>(x_tokens, code_table2, p_stmt, LO_);
    masked_mean_kernel<<<NM_, E_>>>(mini_tokens, code_table, p_mini, LM_);

    // q,k,v,skip projections
    {
        dim3 grid(NM_ / 64, E_ / 64);
        sgemm64<<<grid, 256>>>(p_mini, Wq, bq, p_q, NM_, E_, E_, 0);
        sgemm64<<<grid, 256>>>(p_mini, Wk, bk, p_k, NM_, E_, E_, 0);
        sgemm64<<<grid, 256>>>(p_mini, Wv, bv, p_v, NM_, E_, E_, 0);
        sgemm64<<<grid, 256>>>(p_mini, Wskip, bskip, p_hidden, NM_, E_, E_, 0);
    }

    // transformer conv edge softmax + aggregation
    edge_score_kernel<<<EM_, E_>>>(mini_src, mini_dst);
    edge_exp_kernel<<<(EM_ * H_ + 255) / 256, 256>>>(mini_dst);
    edge_agg_kernel<<<EM_, E_>>>(mini_src, mini_dst);

    // global attention (segments of 8) fused with (attn + stmt)*0.5
    gattn8_kernel<<<NO_ / 8, 256>>>(Wg, bg);

    // degree / norm for GCN
    deg_kernel<<<(EO_ + 255) / 256, 256>>>(dst);
    dinv_kernel<<<(NO_ + 255) / 256, 256>>>();

    // GCN layer 1: xw1 = mini_fn @ W2 ; aggregate ; (relu applied at next GEMM load)
    {
        dim3 grid(NO_ / 64, HID_ / 64);
        sgemm64<<<grid, 256>>>(p_minifn, W2, nullptr, p_xw1, NO_, E_, HID_, 0);
    }
    gcn_init_kernel<<<NO_, HID_>>>(p_xw1, b2, p_gc1, HID_);
    gcn_edge_kernel<<<EO_, HID_>>>(src, dst, p_xw1, p_gc1, HID_);

    // GCN layer 2: xw2 = relu(gc1) @ W3 ; aggregate
    {
        dim3 grid(NO_ / 64, E_ / 64);
        sgemm64<<<grid, 256>>>(p_gc1, W3, nullptr, p_xw2, NO_, HID_, E_, 1);
    }
    gcn_init_kernel<<<NO_, E_>>>(p_xw2, b3, p_fs, E_);
    gcn_edge_kernel<<<EO_, E_>>>(src, dst, p_xw2, p_fs, E_);

    // global attention (segments of 40) -> fn_repr
    gattn40_kernel<<<B_, E_>>>(Wg, bg);

    // cosine similarity -> out[256]
    cos_kernel<<<B_ / 8, 256>>>(out);
    (void)in_sizes; (void)n_in; (void)out_size;
}

// round 2
// speedup vs baseline: 1.3353x; 1.3353x over previous
#include <cuda_runtime.h>

#define B_   256
#define LD_  64
#define NO_  10240
#define LO_  32
#define NM_  81920
#define LM_  16
#define EO_  81920
#define EM_  327680
#define E_   128
#define HID_ 256
#define H_   8
#define Dh_  16

// ---------------- scratch (device globals; no allocation allowed) ----------------
__device__ float g_hn[B_ * E_];
__device__ float g_stmt[NO_ * E_];
__device__ float g_mini[NM_ * E_];
__device__ float g_q[NM_ * E_];
__device__ float g_k[NM_ * E_];
__device__ float g_v[NM_ * E_];
__device__ float g_hidden[NM_ * E_];     // skip output, then += attention agg
__device__ float g_minifn[NO_ * E_];
__device__ float g_dinv[NO_];
__device__ float g_xw1[NO_ * HID_];
__device__ float g_gc1[NO_ * HID_];
__device__ float g_xw2[NO_ * E_];
__device__ float g_fs[NO_ * E_];
__device__ float g_fn[B_ * E_];

// CSR scratch
__device__ int g_deg_m[NM_];
__device__ int g_off_m[NM_ + 1];
__device__ int g_pos_m[NM_];
__device__ int g_csr_m[EM_];
__device__ int g_deg_o[NO_];
__device__ int g_off_o[NO_ + 1];
__device__ int g_pos_o[NO_];
__device__ int g_csr_o[EO_];

// ---------------- init ----------------
__global__ void zero_deg_kernel() {
    int i = blockIdx.x * blockDim.x + threadIdx.x;
    if (i < NM_) g_deg_m[i] = 0;
    if (i < NO_) g_deg_o[i] = 0;
}

__global__ void count_kernel(const int* __restrict__ dst, int* __restrict__ deg, int ne) {
    int e = blockIdx.x * blockDim.x + threadIdx.x;
    if (e < ne) atomicAdd(&deg[dst[e]], 1);
}

// single-block exclusive scan; n divisible by 1024
__global__ void scan_kernel(const int* __restrict__ deg, int* __restrict__ off,
                            int* __restrict__ pos, int n) {
    __shared__ int warpsum[32];
    int tid = threadIdx.x;              // 1024 threads
    int items = n >> 10;
    int base = tid * items;
    int sum = 0;
    for (int i = 0; i < items; i++) sum += deg[base + i];
    int lane = tid & 31, wid = tid >> 5;
    int v = sum;
#pragma unroll
    for (int s = 1; s < 32; s <<= 1) {
        int t = __shfl_up_sync(0xffffffffu, v, s);
        if (lane >= s) v += t;
    }
    if (lane == 31) warpsum[wid] = v;
    __syncthreads();
    if (wid == 0) {
        int w = warpsum[lane];
#pragma unroll
        for (int s = 1; s < 32; s <<= 1) {
            int t = __shfl_up_sync(0xffffffffu, w, s);
            if (lane >= s) w += t;
        }
        warpsum[lane] = w;
    }
    __syncthreads();
    int excl = (v - sum) + (wid > 0 ? warpsum[wid - 1] : 0);
    int run = excl;
    for (int i = 0; i < items; i++) {
        off[base + i] = run;
        pos[base + i] = run;
        run += deg[base + i];
    }
    if (tid == 1023) off[n] = run;
}

__global__ void scatter_kernel(const int* __restrict__ src, const int* __restrict__ dst,
                               int* __restrict__ pos, int* __restrict__ csr, int ne) {
    int e = blockIdx.x * blockDim.x + threadIdx.x;
    if (e < ne) {
        int t = dst[e];
        int slot = atomicAdd(&pos[t], 1);
        csr[slot] = src[e];
    }
}

__global__ void dinv_kernel() {
    int i = blockIdx.x * blockDim.x + threadIdx.x;
    if (i < NO_) g_dinv[i] = rsqrtf((float)(g_deg_o[i] + 1));
}

// ---------------- masked mean embedding pool ----------------
__global__ void masked_mean_kernel(const int* __restrict__ tok,
                                   const float* __restrict__ table,
                                   float* __restrict__ out, int L) {
    __shared__ int ts[64];
    int n = blockIdx.x;
    int d = threadIdx.x;
    if (d < L) ts[d] = tok[n * L + d];
    __syncthreads();
    float acc = 0.f;
    int cnt = 0;
    for (int j = 0; j < L; j++) {
        int t = ts[j];
        if (t != 0) { acc += table[t * E_ + d]; cnt++; }
    }
    out[(size_t)n * E_ + d] = acc / (float)(cnt > 1 ? cnt : 1);
}

// ---------------- SGEMM 128x128 tile, 8x8 microtile, 256 threads ----------------
__global__ void sgemm128(const float* __restrict__ A, const float* __restrict__ W,
                         const float* __restrict__ bias, float* __restrict__ C,
                         int N, int K, int M, int reluA) {
    __shared__ float As[8][128];
    __shared__ float Bs[8][128];
    int tid = threadIdx.x;
    int tx = tid & 15, ty = tid >> 4;
    int row0 = blockIdx.x * 128, col0 = blockIdx.y * 128;
    int arow = tid >> 1;
    int acol = (tid & 1) * 4;
    int brow = tid >> 5;
    int bcol = (tid & 31) * 4;
    float acc[8][8] = {};
    for (int kt = 0; kt < K; kt += 8) {
        float4 av = *(const float4*)&A[(size_t)(row0 + arow) * K + kt + acol];
        if (reluA) {
            av.x = fmaxf(av.x, 0.f); av.y = fmaxf(av.y, 0.f);
            av.z = fmaxf(av.z, 0.f); av.w = fmaxf(av.w, 0.f);
        }
        As[acol + 0][arow] = av.x;
        As[acol + 1][arow] = av.y;
        As[acol + 2][arow] = av.z;
        As[acol + 3][arow] = av.w;
        float4 bv = *(const float4*)&W[(size_t)(kt + brow) * M + col0 + bcol];
        *(float4*)&Bs[brow][bcol] = bv;
        __syncthreads();
#pragma unroll
        for (int k = 0; k < 8; k++) {
            float a[8], b[8];
            *(float4*)&a[0] = *(const float4*)&As[k][ty * 8];
            *(float4*)&a[4] = *(const float4*)&As[k][ty * 8 + 4];
            *(float4*)&b[0] = *(const float4*)&Bs[k][tx * 8];
            *(float4*)&b[4] = *(const float4*)&Bs[k][tx * 8 + 4];
#pragma unroll
            for (int i = 0; i < 8; i++)
#pragma unroll
                for (int j = 0; j < 8; j++) acc[i][j] += a[i] * b[j];
        }
        __syncthreads();
    }
#pragma unroll
    for (int i = 0; i < 8; i++) {
        int row = row0 + ty * 8 + i;
#pragma unroll
        for (int j4 = 0; j4 < 2; j4++) {
            int col = col0 + tx * 8 + j4 * 4;
            float4 bv = bias ? *(const float4*)&bias[col] : make_float4(0.f, 0.f, 0.f, 0.f);
            float4 o;
            o.x = acc[i][j4 * 4 + 0] + bv.x;
            o.y = acc[i][j4 * 4 + 1] + bv.y;
            o.z = acc[i][j4 * 4 + 2] + bv.z;
            o.w = acc[i][j4 * 4 + 3] + bv.w;
            *(float4*)&C[(size_t)row * M + col] = o;
        }
    }
}

// ---------------- fused transformer-conv attention (one warp per dst node) -------
// online softmax over the node's incoming edges; adds result onto g_hidden (skip)
__global__ void attn_kernel() {
    int warp = threadIdx.x >> 5, lane = threadIdx.x & 31;
    int t = blockIdx.x * 8 + warp;
    const float4* q4 = (const float4*)g_q;
    const float4* k4 = (const float4*)g_k;
    const float4* v4 = (const float4*)g_v;
    float4 qv = q4[(size_t)t * 32 + lane];
    float m = -1e30f, ss = 0.f;
    float4 acc = {0.f, 0.f, 0.f, 0.f};
    int beg = g_off_m[t], end = g_off_m[t + 1];
    for (int i = beg; i < end; i++) {
        int s = g_csr_m[i];
        float4 kv = k4[(size_t)s * 32 + lane];
        float p = qv.x * kv.x + qv.y * kv.y + qv.z * kv.z + qv.w * kv.w;
        p += __shfl_xor_sync(0xffffffffu, p, 1);
        p += __shfl_xor_sync(0xffffffffu, p, 2);     // per-head (4-lane group) sum
        float sc = p * 0.25f;                         // 1/sqrt(Dh)
        float mn = fmaxf(m, sc);
        float scale = expf(m - mn);
        float w = expf(sc - mn);
        float4 vv = v4[(size_t)s * 32 + lane];
        ss = ss * scale + w;
        acc.x = acc.x * scale + w * vv.x;
        acc.y = acc.y * scale + w * vv.y;
        acc.z = acc.z * scale + w * vv.z;
        acc.w = acc.w * scale + w * vv.w;
        m = mn;
    }
    float inv = 1.f / (ss + 1e-16f);
    float4* h4 = (float4*)g_hidden;
    float4 h = h4[(size_t)t * 32 + lane];
    h.x += acc.x * inv; h.y += acc.y * inv;
    h.z += acc.z * inv; h.w += acc.w * inv;
    h4[(size_t)t * 32 + lane] = h;
}

// ---------------- global attention over contiguous segments of 8 (mini->NO) ------
__global__ void gattn8_kernel(const float* __restrict__ Wg, const float* __restrict__ bg) {
    int warp = threadIdx.x >> 5;
    int lane = threadIdx.x & 31;
    int n = blockIdx.x * 8 + warp;
    const float4* x4 = (const float4*)g_hidden;
    float4 wg = ((const float4*)Wg)[lane];
    float bgv = bg[0];
    float4 xr[8];
    float g[8];
#pragma unroll
    for (int j = 0; j < 8; j++) {
        float4 xv = x4[(size_t)(n * 8 + j) * 32 + lane];
        xr[j] = xv;
        float p = xv.x * wg.x + xv.y * wg.y + xv.z * wg.z + xv.w * wg.w;
#pragma unroll
        for (int off = 16; off; off >>= 1) p += __shfl_xor_sync(0xffffffffu, p, off);
        g[j] = p + bgv;
    }
    float m = g[0];
#pragma unroll
    for (int j = 1; j < 8; j++) m = fmaxf(m, g[j]);
    float ej[8], s = 0.f;
#pragma unroll
    for (int j = 0; j < 8; j++) { ej[j] = expf(g[j] - m); s += ej[j]; }
    float inv = 1.f / (s + 1e-16f);
    float4 o = {0.f, 0.f, 0.f, 0.f};
#pragma unroll
    for (int j = 0; j < 8; j++) {
        float a = ej[j] * inv;
        o.x += a * xr[j].x; o.y += a * xr[j].y; o.z += a * xr[j].z; o.w += a * xr[j].w;
    }
    float4 st = ((const float4*)g_stmt)[(size_t)n * 32 + lane];
    float4 res = {(o.x + st.x) * 0.5f, (o.y + st.y) * 0.5f,
                  (o.z + st.z) * 0.5f, (o.w + st.w) * 0.5f};
    ((float4*)g_minifn)[(size_t)n * 32 + lane] = res;
}

// ---------------- GCN gather (one warp per node, CSR, no atomics) -----------------
__global__ void gcn_gather_kernel(const float* __restrict__ xw, const float* __restrict__ bias,
                                  float* __restrict__ out, int Mv4) {
    int warp = threadIdx.x >> 5, lane = threadIdx.x & 31;
    int t = blockIdx.x * 8 + warp;
    float di = g_dinv[t];
    int beg = g_off_o[t], end = g_off_o[t + 1];
    const float4* x4 = (const float4*)xw;
    for (int c = lane; c < Mv4; c += 32) {
        float4 a = x4[(size_t)t * Mv4 + c];
        float4 bv = ((const float4*)bias)[c];
        float d2 = di * di;
        float4 acc = {a.x * d2 + bv.x, a.y * d2 + bv.y, a.z * d2 + bv.z, a.w * d2 + bv.w};
        for (int i = beg; i < end; i++) {
            int s = g_csr_o[i];
            float nr = g_dinv[s] * di;
            float4 x = x4[(size_t)s * Mv4 + c];
            acc.x += nr * x.x; acc.y += nr * x.y;
            acc.z += nr * x.z; acc.w += nr * x.w;
        }
        ((float4*)out)[(size_t)t * Mv4 + c] = acc;
    }
}

// ---------------- global attention over contiguous segments of 40 (NO->B) --------
__global__ void gattn40_kernel(const float* __restrict__ Wg, const float* __restrict__ bg) {
    __shared__ float gate[40];
    __shared__ float alpha[40];
    __shared__ float ms[2];
    int b = blockIdx.x;
    int tid = threadIdx.x;  // 128
    int warp = tid >> 5, lane = tid & 31;
    float4 wg = ((const float4*)Wg)[lane];
    for (int j = warp; j < 40; j += 4) {
        float4 xv = ((const float4*)g_fs)[(size_t)(b * 40 + j) * 32 + lane];
        float p = xv.x * wg.x + xv.y * wg.y + xv.z * wg.z + xv.w * wg.w;
#pragma unroll
        for (int off = 16; off; off >>= 1) p += __shfl_xor_sync(0xffffffffu, p, off);
        if (lane == 0) gate[j] = p + bg[0];
    }
    __syncthreads();
    if (tid == 0) {
        float m = gate[0];
        for (int j = 1; j < 40; j++) m = fmaxf(m, gate[j]);
        float s = 0.f;
        for (int j = 0; j < 40; j++) s += expf(gate[j] - m);
        ms[0] = m; ms[1] = s;
    }
    __syncthreads();
    if (tid < 40) alpha[tid] = expf(gate[tid] - ms[0]) / (ms[1] + 1e-16f);
    __syncthreads();
    float acc = 0.f;
    for (int j = 0; j < 40; j++)
        acc += alpha[j] * g_fs[(size_t)(b * 40 + j) * E_ + tid];
    g_fn[(size_t)b * E_ + tid] = acc;
}

// ---------------- cosine similarity ----------------
__global__ void cos_kernel(float* __restrict__ out) {
    int warp = threadIdx.x >> 5, lane = threadIdx.x & 31;
    int b = blockIdx.x * 8 + warp;
    float4 a4 = ((const float4*)g_fn)[(size_t)b * 32 + lane];
    float4 b4 = ((const float4*)g_hn)[(size_t)b * 32 + lane];
    float dt = a4.x * b4.x + a4.y * b4.y + a4.z * b4.z + a4.w * b4.w;
    float na = a4.x * a4.x + a4.y * a4.y + a4.z * a4.z + a4.w * a4.w;
    float nb = b4.x * b4.x + b4.y * b4.y + b4.z * b4.z + b4.w * b4.w;
#pragma unroll
    for (int off = 16; off; off >>= 1) {
        dt += __shfl_xor_sync(0xffffffffu, dt, off);
        na += __shfl_xor_sync(0xffffffffu, na, off);
        nb += __shfl_xor_sync(0xffffffffu, nb, off);
    }
    if (lane == 0)
        out[b] = dt / (fmaxf(sqrtf(na), 1e-8f) * fmaxf(sqrtf(nb), 1e-8f));
}

// ---------------- launch ----------------
extern "C" void kernel_launch(void* const* d_in, const int* in_sizes, int n_in,
                              void* d_out, int out_size) {
    const int* desc_tokens = (const int*)d_in[0];
    const int* x_tokens    = (const int*)d_in[1];
    const int* mini_tokens = (const int*)d_in[2];
    const int* src         = (const int*)d_in[3];
    const int* dst         = (const int*)d_in[4];
    const int* mini_src    = (const int*)d_in[5];
    const int* mini_dst    = (const int*)d_in[6];
    const float* desc_table  = (const float*)d_in[9];
    const float* code_table  = (const float*)d_in[10];
    const float* code_table2 = (const float*)d_in[11];
    const float* Wq = (const float*)d_in[12]; const float* bq = (const float*)d_in[13];
    const float* Wk = (const float*)d_in[14]; const float* bk = (const float*)d_in[15];
    const float* Wv = (const float*)d_in[16]; const float* bv = (const float*)d_in[17];
    const float* Wskip = (const float*)d_in[18]; const float* bskip = (const float*)d_in[19];
    const float* W2 = (const float*)d_in[20]; const float* b2 = (const float*)d_in[21];
    const float* W3 = (const float*)d_in[22]; const float* b3 = (const float*)d_in[23];
    const float* Wg = (const float*)d_in[24]; const float* bg = (const float*)d_in[25];
    float* out = (float*)d_out;

    float *p_mini, *p_q, *p_k, *p_v, *p_hidden, *p_hn, *p_stmt, *p_minifn;
    float *p_xw1, *p_gc1, *p_xw2, *p_fs;
    cudaGetSymbolAddress((void**)&p_mini, g_mini);
    cudaGetSymbolAddress((void**)&p_q, g_q);
    cudaGetSymbolAddress((void**)&p_k, g_k);
    cudaGetSymbolAddress((void**)&p_v, g_v);
    cudaGetSymbolAddress((void**)&p_hidden, g_hidden);
    cudaGetSymbolAddress((void**)&p_hn, g_hn);
    cudaGetSymbolAddress((void**)&p_stmt, g_stmt);
    cudaGetSymbolAddress((void**)&p_minifn, g_minifn);
    cudaGetSymbolAddress((void**)&p_xw1, g_xw1);
    cudaGetSymbolAddress((void**)&p_gc1, g_gc1);
    cudaGetSymbolAddress((void**)&p_xw2, g_xw2);
    cudaGetSymbolAddress((void**)&p_fs, g_fs);

    int *p_deg_m, *p_off_m, *p_pos_m, *p_csr_m;
    int *p_deg_o, *p_off_o, *p_pos_o, *p_csr_o;
    cudaGetSymbolAddress((void**)&p_deg_m, g_deg_m);
    cudaGetSymbolAddress((void**)&p_off_m, g_off_m);
    cudaGetSymbolAddress((void**)&p_pos_m, g_pos_m);
    cudaGetSymbolAddress((void**)&p_csr_m, g_csr_m);
    cudaGetSymbolAddress((void**)&p_deg_o, g_deg_o);
    cudaGetSymbolAddress((void**)&p_off_o, g_off_o);
    cudaGetSymbolAddress((void**)&p_pos_o, g_pos_o);
    cudaGetSymbolAddress((void**)&p_csr_o, g_csr_o);

    // ---- CSR build ----
    zero_deg_kernel<<<(NM_ + 255) / 256, 256>>>();
    count_kernel<<<(EM_ + 255) / 256, 256>>>(mini_dst, p_deg_m, EM_);
    count_kernel<<<(EO_ + 255) / 256, 256>>>(dst, p_deg_o, EO_);
    scan_kernel<<<1, 1024>>>(p_deg_m, p_off_m, p_pos_m, NM_);
    scan_kernel<<<1, 1024>>>(p_deg_o, p_off_o, p_pos_o, NO_);
    dinv_kernel<<<(NO_ + 255) / 256, 256>>>();
    scatter_kernel<<<(EM_ + 255) / 256, 256>>>(mini_src, mini_dst, p_pos_m, p_csr_m, EM_);
    scatter_kernel<<<(EO_ + 255) / 256, 256>>>(src, dst, p_pos_o, p_csr_o, EO_);

    // ---- embeddings ----
    masked_mean_kernel<<<B_, E_>>>(desc_tokens, desc_table, p_hn, LD_);
    masked_mean_kernel<<<NO_, E_>>>(x_tokens, code_table2, p_stmt, LO_);
    masked_mean_kernel<<<NM_, E_>>>(mini_tokens, code_table, p_mini, LM_);

    // ---- q,k,v,skip projections ----
    {
        dim3 grid(NM_ / 128, E_ / 128);
        sgemm128<<<grid, 256>>>(p_mini, Wq, bq, p_q, NM_, E_, E_, 0);
        sgemm128<<<grid, 256>>>(p_mini, Wk, bk, p_k, NM_, E_, E_, 0);
        sgemm128<<<grid, 256>>>(p_mini, Wv, bv, p_v, NM_, E_, E_, 0);
        sgemm128<<<grid, 256>>>(p_mini, Wskip, bskip, p_hidden, NM_, E_, E_, 0);
    }

    // ---- fused attention (online softmax per dst node) ----
    attn_kernel<<<NM_ / 8, 256>>>();

    // ---- global attention (segments of 8) fused with (attn + stmt)*0.5 ----
    gattn8_kernel<<<NO_ / 8, 256>>>(Wg, bg);

    // ---- GCN layer 1 ----
    {
        dim3 grid(NO_ / 128, HID_ / 128);
        sgemm128<<<grid, 256>>>(p_minifn, W2, nullptr, p_xw1, NO_, E_, HID_, 0);
    }
    gcn_gather_kernel<<<NO_ / 8, 256>>>(p_xw1, b2, p_gc1, HID_ / 4);

    // ---- GCN layer 2 (relu applied on A load) ----
    {
        dim3 grid(NO_ / 128, E_ / 128);
        sgemm128<<<grid, 256>>>(p_gc1, W3, nullptr, p_xw2, NO_, HID_, E_, 1);
    }
    gcn_gather_kernel<<<NO_ / 8, 256>>>(p_xw2, b3, p_fs, E_ / 4);

    // ---- readout ----
    gattn40_kernel<<<B_, E_>>>(Wg, bg);
    cos_kernel<<<B_ / 8, 256>>>(out);
    (void)in_sizes; (void)n_in; (void)out_size;
}

// round 3
// speedup vs baseline: 1.8831x; 1.4102x over previous
#include <cuda_runtime.h>

#define B_   256
#define LD_  64
#define NO_  10240
#define LO_  32
#define NM_  81920
#define LM_  16
#define EO_  81920
#define EM_  327680
#define E_   128
#define HID_ 256
#define H_   8
#define Dh_  16

// ---------------- scratch ----------------
__device__ float g_hn[B_ * E_];
__device__ float g_stmt[NO_ * E_];
__device__ float g_mini[NM_ * E_];
__device__ float g_q[NM_ * E_];
__device__ float g_k[NM_ * E_];
__device__ float g_v[NM_ * E_];
__device__ float g_hidden[NM_ * E_];
__device__ float g_minifn[NO_ * E_];
__device__ float g_dinv[NO_];
__device__ float g_xw1[NO_ * HID_];
__device__ float g_gc1[NO_ * HID_];
__device__ float g_xw2[NO_ * E_];
__device__ float g_fs[NO_ * E_];
__device__ float g_fn[B_ * E_];

__device__ int g_deg_m[NM_];
__device__ int g_off_m[NM_ + 1];
__device__ int g_pos_m[NM_];
__device__ int g_csr_m[EM_];
__device__ int g_bsum_m[256];
__device__ int g_deg_o[NO_];
__device__ int g_off_o[NO_ + 1];
__device__ int g_pos_o[NO_];
__device__ int g_csr_o[EO_];
__device__ int g_bsum_o[256];

// ---------------- f32x2 packed math ----------------
#define FMA_F32X2(d, a, b, c) \
    asm("fma.rn.f32x2 %0, %1, %2, %3;" : "=l"(d) : "l"(a), "l"(b), "l"(c))
#define PACK_F32X2(out, lo, hi) \
    asm("mov.b64 %0, {%1, %2};" : "=l"(out) : "r"(lo), "r"(hi))
#define UNPACK_F32X2(lo, hi, in) \
    asm("mov.b64 {%0, %1}, %2;" : "=r"(lo), "=r"(hi) : "l"(in))

// ---------------- CSR build ----------------
__global__ void zero_deg_kernel() {
    int i = blockIdx.x * blockDim.x + threadIdx.x;
    if (i < NM_) g_deg_m[i] = 0;
    if (i < NO_) g_deg_o[i] = 0;
}

__global__ void count_kernel(const int* __restrict__ dst, int* __restrict__ deg, int ne) {
    int e = blockIdx.x * blockDim.x + threadIdx.x;
    if (e < ne) atomicAdd(&deg[dst[e]], 1);
}

// phase 1: 256 threads scan 1024 elements per block -> local exclusive in off, block total in bsum
__global__ void scan_local_kernel(const int* __restrict__ deg, int* __restrict__ off,
                                  int* __restrict__ bsum) {
    __shared__ int ws[8];
    int tid = threadIdx.x;
    int base = blockIdx.x * 1024 + tid * 4;
    int4 d = *(const int4*)&deg[base];
    int s = d.x + d.y + d.z + d.w;
    int lane = tid & 31, wid = tid >> 5;
    int v = s;
#pragma unroll
    for (int o = 1; o < 32; o <<= 1) {
        int t = __shfl_up_sync(0xffffffffu, v, o);
        if (lane >= o) v += t;
    }
    if (lane == 31) ws[wid] = v;
    __syncthreads();
    if (tid == 0) {
        int run = 0;
#pragma unroll
        for (int w = 0; w < 8; w++) { int t = ws[w]; ws[w] = run; run += t; }
    }
    __syncthreads();
    int excl = v - s + ws[wid];
    int4 o4;
    o4.x = excl;
    o4.y = excl + d.x;
    o4.z = o4.y + d.y;
    o4.w = o4.z + d.z;
    *(int4*)&off[base] = o4;
    if (tid == 255) bsum[blockIdx.x] = excl + s;
}

// phase 2: one block scans <=128 block sums to exclusive, writes grand total to off[n]
__global__ void scan_bsums_kernel(int* __restrict__ bsum, int nb, int* __restrict__ off, int n) {
    __shared__ int sh[128];
    int tid = threadIdx.x;  // 128
    int val = (tid < nb) ? bsum[tid] : 0;
    sh[tid] = val;
    __syncthreads();
    int acc = val;
    for (int o = 1; o < 128; o <<= 1) {
        int t = (tid >= o) ? sh[tid - o] : 0;
        __syncthreads();
        acc += t;
        sh[tid] = acc;
        __syncthreads();
    }
    if (tid < nb) bsum[tid] = acc - val;          // exclusive
    if (tid == 127) off[n] = sh[127];             // grand total (== ne)
}

// phase 3: add block offsets, mirror into pos
__global__ void scan_add_kernel(int* __restrict__ off, int* __restrict__ pos,
                                const int* __restrict__ bsum, int n) {
    int i = blockIdx.x * blockDim.x + threadIdx.x;
    if (i < n) {
        int v = off[i] + bsum[i >> 10];
        off[i] = v;
        pos[i] = v;
    }
}

__global__ void scatter_kernel(const int* __restrict__ src, const int* __restrict__ dst,
                               int* __restrict__ pos, int* __restrict__ csr, int ne) {
    int e = blockIdx.x * blockDim.x + threadIdx.x;
    if (e < ne) {
        int t = dst[e];
        int slot = atomicAdd(&pos[t], 1);
        csr[slot] = src[e];
    }
}

__global__ void dinv_kernel() {
    int i = blockIdx.x * blockDim.x + threadIdx.x;
    if (i < NO_) g_dinv[i] = rsqrtf((float)(g_deg_o[i] + 1));
}

// ---------------- masked mean embedding pool ----------------
__global__ void masked_mean_kernel(const int* __restrict__ tok,
                                   const float* __restrict__ table,
                                   float* __restrict__ out, int L) {
    __shared__ int ts[64];
    int n = blockIdx.x;
    int d = threadIdx.x;
    if (d < L) ts[d] = tok[n * L + d];
    __syncthreads();
    float acc = 0.f;
    int cnt = 0;
    for (int j = 0; j < L; j++) {
        int t = ts[j];
        if (t != 0) { acc += table[t * E_ + d]; cnt++; }
    }
    out[(size_t)n * E_ + d] = acc / (float)(cnt > 1 ? cnt : 1);
}

// ---------------- SGEMM 128x128 tile, 8x8 microtile, f32x2 FMA ----------------
__device__ __forceinline__ void sgemm128_body(
    const float* __restrict__ A, const float* __restrict__ W,
    const float* __restrict__ bias, float* __restrict__ C,
    int K, int M, int reluA, int row0, int col0) {
    __shared__ __align__(16) float As[8][128];
    __shared__ __align__(16) float Bs[8][128];
    int tid = threadIdx.x;
    int tx = tid & 15, ty = tid >> 4;
    int arow = tid >> 1;
    int acol = (tid & 1) * 4;
    int brow = tid >> 5;
    int bcol = (tid & 31) * 4;
    unsigned long long acc2[8][4];
#pragma unroll
    for (int i = 0; i < 8; i++)
#pragma unroll
        for (int j = 0; j < 4; j++) acc2[i][j] = 0ull;

    for (int kt = 0; kt < K; kt += 8) {
        float4 av = *(const float4*)&A[(size_t)(row0 + arow) * K + kt + acol];
        if (reluA) {
            av.x = fmaxf(av.x, 0.f); av.y = fmaxf(av.y, 0.f);
            av.z = fmaxf(av.z, 0.f); av.w = fmaxf(av.w, 0.f);
        }
        As[acol + 0][arow] = av.x;
        As[acol + 1][arow] = av.y;
        As[acol + 2][arow] = av.z;
        As[acol + 3][arow] = av.w;
        *(float4*)&Bs[brow][bcol] = *(const float4*)&W[(size_t)(kt + brow) * M + col0 + bcol];
        __syncthreads();
#pragma unroll
        for (int k = 0; k < 8; k++) {
            float a[8];
            *(float4*)&a[0] = *(const float4*)&As[k][ty * 8];
            *(float4*)&a[4] = *(const float4*)&As[k][ty * 8 + 4];
            ulonglong2 bA = *(const ulonglong2*)&Bs[k][tx * 8];
            ulonglong2 bB = *(const ulonglong2*)&Bs[k][tx * 8 + 4];
            unsigned long long b2[4] = {bA.x, bA.y, bB.x, bB.y};
#pragma unroll
            for (int i = 0; i < 8; i++) {
                unsigned long long a2;
                unsigned int ab = __float_as_uint(a[i]);
                PACK_F32X2(a2, ab, ab);
#pragma unroll
                for (int j = 0; j < 4; j++)
                    FMA_F32X2(acc2[i][j], a2, b2[j], acc2[i][j]);
            }
        }
        __syncthreads();
    }
#pragma unroll
    for (int i = 0; i < 8; i++) {
        int row = row0 + ty * 8 + i;
        float r[8];
#pragma unroll
        for (int j = 0; j < 4; j++) {
            unsigned int lo, hi;
            UNPACK_F32X2(lo, hi, acc2[i][j]);
            r[2 * j] = __uint_as_float(lo);
            r[2 * j + 1] = __uint_as_float(hi);
        }
#pragma unroll
        for (int j4 = 0; j4 < 2; j4++) {
            int col = col0 + tx * 8 + j4 * 4;
            float4 bv = bias ? *(const float4*)&bias[col] : make_float4(0.f, 0.f, 0.f, 0.f);
            float4 o;
            o.x = r[j4 * 4 + 0] + bv.x;
            o.y = r[j4 * 4 + 1] + bv.y;
            o.z = r[j4 * 4 + 2] + bv.z;
            o.w = r[j4 * 4 + 3] + bv.w;
            *(float4*)&C[(size_t)row * M + col] = o;
        }
    }
}

__global__ __launch_bounds__(256) void sgemm128(
    const float* __restrict__ A, const float* __restrict__ W,
    const float* __restrict__ bias, float* __restrict__ C,
    int K, int M, int reluA) {
    sgemm128_body(A, W, bias, C, K, M, reluA, blockIdx.x * 128, blockIdx.y * 128);
}

// fused QKV+skip: blockIdx.z selects weight/bias/output
__global__ __launch_bounds__(256) void sgemm128_qkvs(
    const float* __restrict__ A,
    const float* __restrict__ Wq, const float* __restrict__ bq, float* __restrict__ Cq,
    const float* __restrict__ Wk, const float* __restrict__ bk, float* __restrict__ Ck,
    const float* __restrict__ Wv, const float* __restrict__ bv, float* __restrict__ Cv,
    const float* __restrict__ Ws, const float* __restrict__ bs, float* __restrict__ Cs) {
    const float* W; const float* bias; float* C;
    switch (blockIdx.z) {
        case 0: W = Wq; bias = bq; C = Cq; break;
        case 1: W = Wk; bias = bk; C = Ck; break;
        case 2: W = Wv; bias = bv; C = Cv; break;
        default: W = Ws; bias = bs; C = Cs; break;
    }
    sgemm128_body(A, W, bias, C, E_, E_, 0, blockIdx.x * 128, 0);
}

// ---------------- fused transformer-conv attention (one warp per dst node) -------
__global__ void attn_kernel() {
    int warp = threadIdx.x >> 5, lane = threadIdx.x & 31;
    int t = blockIdx.x * 8 + warp;
    const float4* q4 = (const float4*)g_q;
    const float4* k4 = (const float4*)g_k;
    const float4* v4 = (const float4*)g_v;
    float4 qv = q4[(size_t)t * 32 + lane];
    float m = -1e30f, ss = 0.f;
    float4 acc = {0.f, 0.f, 0.f, 0.f};
    int beg = g_off_m[t], end = g_off_m[t + 1];
    for (int i = beg; i < end; i++) {
        int s = g_csr_m[i];
        float4 kv = k4[(size_t)s * 32 + lane];
        float p = qv.x * kv.x + qv.y * kv.y + qv.z * kv.z + qv.w * kv.w;
        p += __shfl_xor_sync(0xffffffffu, p, 1);
        p += __shfl_xor_sync(0xffffffffu, p, 2);
        float sc = p * 0.25f;
        float mn = fmaxf(m, sc);
        float scale = expf(m - mn);
        float w = expf(sc - mn);
        float4 vv = v4[(size_t)s * 32 + lane];
        ss = ss * scale + w;
        acc.x = acc.x * scale + w * vv.x;
        acc.y = acc.y * scale + w * vv.y;
        acc.z = acc.z * scale + w * vv.z;
        acc.w = acc.w * scale + w * vv.w;
        m = mn;
    }
    float inv = 1.f / (ss + 1e-16f);
    float4* h4 = (float4*)g_hidden;
    float4 h = h4[(size_t)t * 32 + lane];
    h.x += acc.x * inv; h.y += acc.y * inv;
    h.z += acc.z * inv; h.w += acc.w * inv;
    h4[(size_t)t * 32 + lane] = h;
}

// ---------------- global attention (segments of 8) ----------------
__global__ void gattn8_kernel(const float* __restrict__ Wg, const float* __restrict__ bg) {
    int warp = threadIdx.x >> 5;
    int lane = threadIdx.x & 31;
    int n = blockIdx.x * 8 + warp;
    const float4* x4 = (const float4*)g_hidden;
    float4 wg = ((const float4*)Wg)[lane];
    float bgv = bg[0];
    float4 xr[8];
    float g[8];
#pragma unroll
    for (int j = 0; j < 8; j++) {
        float4 xv = x4[(size_t)(n * 8 + j) * 32 + lane];
        xr[j] = xv;
        float p = xv.x * wg.x + xv.y * wg.y + xv.z * wg.z + xv.w * wg.w;
#pragma unroll
        for (int off = 16; off; off >>= 1) p += __shfl_xor_sync(0xffffffffu, p, off);
        g[j] = p + bgv;
    }
    float m = g[0];
#pragma unroll
    for (int j = 1; j < 8; j++) m = fmaxf(m, g[j]);
    float ej[8], s = 0.f;
#pragma unroll
    for (int j = 0; j < 8; j++) { ej[j] = expf(g[j] - m); s += ej[j]; }
    float inv = 1.f / (s + 1e-16f);
    float4 o = {0.f, 0.f, 0.f, 0.f};
#pragma unroll
    for (int j = 0; j < 8; j++) {
        float a = ej[j] * inv;
        o.x += a * xr[j].x; o.y += a * xr[j].y; o.z += a * xr[j].z; o.w += a * xr[j].w;
    }
    float4 st = ((const float4*)g_stmt)[(size_t)n * 32 + lane];
    float4 res = {(o.x + st.x) * 0.5f, (o.y + st.y) * 0.5f,
                  (o.z + st.z) * 0.5f, (o.w + st.w) * 0.5f};
    ((float4*)g_minifn)[(size_t)n * 32 + lane] = res;
}

// ---------------- GCN gather ----------------
__global__ void gcn_gather_kernel(const float* __restrict__ xw, const float* __restrict__ bias,
                                  float* __restrict__ out, int Mv4) {
    int warp = threadIdx.x >> 5, lane = threadIdx.x & 31;
    int t = blockIdx.x * 8 + warp;
    float di = g_dinv[t];
    int beg = g_off_o[t], end = g_off_o[t + 1];
    const float4* x4 = (const float4*)xw;
    for (int c = lane; c < Mv4; c += 32) {
        float4 a = x4[(size_t)t * Mv4 + c];
        float4 bv = ((const float4*)bias)[c];
        float d2 = di * di;
        float4 acc = {a.x * d2 + bv.x, a.y * d2 + bv.y, a.z * d2 + bv.z, a.w * d2 + bv.w};
        for (int i = beg; i < end; i++) {
            int s = g_csr_o[i];
            float nr = g_dinv[s] * di;
            float4 x = x4[(size_t)s * Mv4 + c];
            acc.x += nr * x.x; acc.y += nr * x.y;
            acc.z += nr * x.z; acc.w += nr * x.w;
        }
        ((float4*)out)[(size_t)t * Mv4 + c] = acc;
    }
}

// ---------------- global attention (segments of 40) ----------------
__global__ void gattn40_kernel(const float* __restrict__ Wg, const float* __restrict__ bg) {
    __shared__ float gate[40];
    __shared__ float alpha[40];
    __shared__ float ms[2];
    int b = blockIdx.x;
    int tid = threadIdx.x;
    int warp = tid >> 5, lane = tid & 31;
    float4 wg = ((const float4*)Wg)[lane];
    for (int j = warp; j < 40; j += 4) {
        float4 xv = ((const float4*)g_fs)[(size_t)(b * 40 + j) * 32 + lane];
        float p = xv.x * wg.x + xv.y * wg.y + xv.z * wg.z + xv.w * wg.w;
#pragma unroll
        for (int off = 16; off; off >>= 1) p += __shfl_xor_sync(0xffffffffu, p, off);
        if (lane == 0) gate[j] = p + bg[0];
    }
    __syncthreads();
    if (tid == 0) {
        float m = gate[0];
        for (int j = 1; j < 40; j++) m = fmaxf(m, gate[j]);
        float s = 0.f;
        for (int j = 0; j < 40; j++) s += expf(gate[j] - m);
        ms[0] = m; ms[1] = s;
    }
    __syncthreads();
    if (tid < 40) alpha[tid] = expf(gate[tid] - ms[0]) / (ms[1] + 1e-16f);
    __syncthreads();
    float acc = 0.f;
    for (int j = 0; j < 40; j++)
        acc += alpha[j] * g_fs[(size_t)(b * 40 + j) * E_ + tid];
    g_fn[(size_t)b * E_ + tid] = acc;
}

// ---------------- cosine ----------------
__global__ void cos_kernel(float* __restrict__ out) {
    int warp = threadIdx.x >> 5, lane = threadIdx.x & 31;
    int b = blockIdx.x * 8 + warp;
    float4 a4 = ((const float4*)g_fn)[(size_t)b * 32 + lane];
    float4 b4 = ((const float4*)g_hn)[(size_t)b * 32 + lane];
    float dt = a4.x * b4.x + a4.y * b4.y + a4.z * b4.z + a4.w * b4.w;
    float na = a4.x * a4.x + a4.y * a4.y + a4.z * a4.z + a4.w * a4.w;
    float nb = b4.x * b4.x + b4.y * b4.y + b4.z * b4.z + b4.w * b4.w;
#pragma unroll
    for (int off = 16; off; off >>= 1) {
        dt += __shfl_xor_sync(0xffffffffu, dt, off);
        na += __shfl_xor_sync(0xffffffffu, na, off);
        nb += __shfl_xor_sync(0xffffffffu, nb, off);
    }
    if (lane == 0)
        out[b] = dt / (fmaxf(sqrtf(na), 1e-8f) * fmaxf(sqrtf(nb), 1e-8f));
}

// ---------------- launch ----------------
extern "C" void kernel_launch(void* const* d_in, const int* in_sizes, int n_in,
                              void* d_out, int out_size) {
    const int* desc_tokens = (const int*)d_in[0];
    const int* x_tokens    = (const int*)d_in[1];
    const int* mini_tokens = (const int*)d_in[2];
    const int* src         = (const int*)d_in[3];
    const int* dst         = (const int*)d_in[4];
    const int* mini_src    = (const int*)d_in[5];
    const int* mini_dst    = (const int*)d_in[6];
    const float* desc_table  = (const float*)d_in[9];
    const float* code_table  = (const float*)d_in[10];
    const float* code_table2 = (const float*)d_in[11];
    const float* Wq = (const float*)d_in[12]; const float* bq = (const float*)d_in[13];
    const float* Wk = (const float*)d_in[14]; const float* bk = (const float*)d_in[15];
    const float* Wv = (const float*)d_in[16]; const float* bv = (const float*)d_in[17];
    const float* Wskip = (const float*)d_in[18]; const float* bskip = (const float*)d_in[19];
    const float* W2 = (const float*)d_in[20]; const float* b2 = (const float*)d_in[21];
    const float* W3 = (const float*)d_in[22]; const float* b3 = (const float*)d_in[23];
    const float* Wg = (const float*)d_in[24]; const float* bg = (const float*)d_in[25];
    float* out = (float*)d_out;

    float *p_mini, *p_q, *p_k, *p_v, *p_hidden, *p_hn, *p_stmt, *p_minifn;
    float *p_xw1, *p_gc1, *p_xw2, *p_fs;
    cudaGetSymbolAddress((void**)&p_mini, g_mini);
    cudaGetSymbolAddress((void**)&p_q, g_q);
    cudaGetSymbolAddress((void**)&p_k, g_k);
    cudaGetSymbolAddress((void**)&p_v, g_v);
    cudaGetSymbolAddress((void**)&p_hidden, g_hidden);
    cudaGetSymbolAddress((void**)&p_hn, g_hn);
    cudaGetSymbolAddress((void**)&p_stmt, g_stmt);
    cudaGetSymbolAddress((void**)&p_minifn, g_minifn);
    cudaGetSymbolAddress((void**)&p_xw1, g_xw1);
    cudaGetSymbolAddress((void**)&p_gc1, g_gc1);
    cudaGetSymbolAddress((void**)&p_xw2, g_xw2);
    cudaGetSymbolAddress((void**)&p_fs, g_fs);

    int *p_deg_m, *p_off_m, *p_pos_m, *p_csr_m, *p_bsum_m;
    int *p_deg_o, *p_off_o, *p_pos_o, *p_csr_o, *p_bsum_o;
    cudaGetSymbolAddress((void**)&p_deg_m, g_deg_m);
    cudaGetSymbolAddress((void**)&p_off_m, g_off_m);
    cudaGetSymbolAddress((void**)&p_pos_m, g_pos_m);
    cudaGetSymbolAddress((void**)&p_csr_m, g_csr_m);
    cudaGetSymbolAddress((void**)&p_bsum_m, g_bsum_m);
    cudaGetSymbolAddress((void**)&p_deg_o, g_deg_o);
    cudaGetSymbolAddress((void**)&p_off_o, g_off_o);
    cudaGetSymbolAddress((void**)&p_pos_o, g_pos_o);
    cudaGetSymbolAddress((void**)&p_csr_o, g_csr_o);
    cudaGetSymbolAddress((void**)&p_bsum_o, g_bsum_o);

    // ---- CSR build (fast 3-phase scans) ----
    zero_deg_kernel<<<(NM_ + 255) / 256, 256>>>();
    count_kernel<<<(EM_ + 255) / 256, 256>>>(mini_dst, p_deg_m, EM_);
    count_kernel<<<(EO_ + 255) / 256, 256>>>(dst, p_deg_o, EO_);
    scan_local_kernel<<<NM_ / 1024, 256>>>(p_deg_m, p_off_m, p_bsum_m);
    scan_local_kernel<<<NO_ / 1024, 256>>>(p_deg_o, p_off_o, p_bsum_o);
    scan_bsums_kernel<<<1, 128>>>(p_bsum_m, NM_ / 1024, p_off_m, NM_);
    scan_bsums_kernel<<<1, 128>>>(p_bsum_o, NO_ / 1024, p_off_o, NO_);
    scan_add_kernel<<<NM_ / 256, 256>>>(p_off_m, p_pos_m, p_bsum_m, NM_);
    scan_add_kernel<<<NO_ / 256, 256>>>(p_off_o, p_pos_o, p_bsum_o, NO_);
    dinv_kernel<<<(NO_ + 255) / 256, 256>>>();
    scatter_kernel<<<(EM_ + 255) / 256, 256>>>(mini_src, mini_dst, p_pos_m, p_csr_m, EM_);
    scatter_kernel<<<(EO_ + 255) / 256, 256>>>(src, dst, p_pos_o, p_csr_o, EO_);

    // ---- embeddings ----
    masked_mean_kernel<<<B_, E_>>>(desc_tokens, desc_table, p_hn, LD_);
    masked_mean_kernel<<<NO_, E_>>>(x_tokens, code_table2, p_stmt, LO_);
    masked_mean_kernel<<<NM_, E_>>>(mini_tokens, code_table, p_mini, LM_);

    // ---- fused q,k,v,skip projections ----
    {
        dim3 grid(NM_ / 128, 1, 4);
        sgemm128_qkvs<<<grid, 256>>>(p_mini,
                                     Wq, bq, p_q, Wk, bk, p_k,
                                     Wv, bv, p_v, Wskip, bskip, p_hidden);
    }

    // ---- fused attention ----
    attn_kernel<<<NM_ / 8, 256>>>();

    // ---- global attention (segments of 8) ----
    gattn8_kernel<<<NO_ / 8, 256>>>(Wg, bg);

    // ---- GCN layer 1 ----
    {
        dim3 grid(NO_ / 128, HID_ / 128);
        sgemm128<<<grid, 256>>>(p_minifn, W2, nullptr, p_xw1, E_, HID_, 0);
    }
    gcn_gather_kernel<<<NO_ / 8, 256>>>(p_xw1, b2, p_gc1, HID_ / 4);

    // ---- GCN layer 2 ----
    {
        dim3 grid(NO_ / 128, E_ / 128);
        sgemm128<<<grid, 256>>>(p_gc1, W3, nullptr, p_xw2, HID_, E_, 1);
    }
    gcn_gather_kernel<<<NO_ / 8, 256>>>(p_xw2, b3, p_fs, E_ / 4);

    // ---- readout ----
    gattn40_kernel<<<B_, E_>>>(Wg, bg);
    cos_kernel<<<B_ / 8, 256>>>(out);
    (void)in_sizes; (void)n_in; (void)out_size;
}

// round 5
// speedup vs baseline: 2.1403x; 1.1366x over previous
#include <cuda_runtime.h>
#include <cstdint>

#define B_   256
#define LD_  64
#define NO_  10240
#define LO_  32
#define NM_  81920
#define LM_  16
#define EO_  81920
#define EM_  327680
#define E_   128
#define HID_ 256
#define H_   8
#define Dh_  16

// ---------------- scratch ----------------
__device__ float g_hn[B_ * E_];
__device__ float g_stmt[NO_ * E_];
__device__ float g_mini[NM_ * E_];
__device__ float g_q[NM_ * E_];
__device__ float g_k[NM_ * E_];
__device__ float g_v[NM_ * E_];
__device__ float g_hidden[NM_ * E_];
__device__ float g_minifn[NO_ * E_];
__device__ float g_dinv[NO_];
__device__ float g_xw1[NO_ * HID_];
__device__ float g_gc1[NO_ * HID_];
__device__ float g_xw2[NO_ * E_];
__device__ float g_fs[NO_ * E_];
__device__ float g_fn[B_ * E_];

__device__ int g_deg_m[NM_];
__device__ int g_off_m[NM_ + 1];
__device__ int g_pos_m[NM_];
__device__ int g_csr_m[EM_];
__device__ int g_bsum_m[256];
__device__ int g_deg_o[NO_];
__device__ int g_off_o[NO_ + 1];
__device__ int g_pos_o[NO_];
__device__ int g_csr_o[EO_];
__device__ int g_bsum_o[256];

// ---------------- tf32 helpers ----------------
__device__ __forceinline__ uint32_t to_tf32_bits(float x) {
    float r;
    asm("cvt.rna.tf32.f32 %0, %1;" : "=f"(r) : "f"(x));
    return __float_as_uint(r);
}
__device__ __forceinline__ float tf32_val(float x) {
    float r;
    asm("cvt.rna.tf32.f32 %0, %1;" : "=f"(r) : "f"(x));
    return r;
}
__device__ __forceinline__ void mma_tf32(float* d, const uint32_t* a, const uint32_t* b) {
    asm volatile(
        "mma.sync.aligned.m16n8k8.row.col.f32.tf32.tf32.f32 "
        "{%0,%1,%2,%3}, {%4,%5,%6,%7}, {%8,%9}, {%0,%1,%2,%3};"
        : "+f"(d[0]), "+f"(d[1]), "+f"(d[2]), "+f"(d[3])
        : "r"(a[0]), "r"(a[1]), "r"(a[2]), "r"(a[3]), "r"(b[0]), "r"(b[1]));
}

// smem strides chosen so (addr mod 32) is a lane bijection (conflict-free)
#define AS_STRIDE 36   // 32 + 4
#define BS_STRIDE 132  // 128 + 4
#define AS_ELEMS (128 * AS_STRIDE)  // 4608 floats
#define BS_ELEMS (32 * BS_STRIDE)   // 4224 floats
#define MMA_SMEM ((2 * AS_ELEMS + 2 * BS_ELEMS) * 4)  // 70656 bytes

// ---------------- 3xTF32 mma.sync GEMM: C[128 x 128] tile = A@W (+bias) ----------
// A: [*, K] fp32 row-major; W: [K, Ntot] fp32 row-major; K multiple of 32.
// 256 threads = 8 warps (2 in M x 4 in N); warp tile 64x32; 4x4 m16n8k8 tiles.
__device__ void mma_gemm_body(const float* __restrict__ A, const float* __restrict__ W,
                              const float* __restrict__ bias, float* __restrict__ C,
                              int row0, int K, int Ntot, int col0, int relu) {
    extern __shared__ __align__(16) float sm[];
    float* As_hi = sm;
    float* As_lo = As_hi + AS_ELEMS;
    float* Bs_hi = As_lo + AS_ELEMS;
    float* Bs_lo = Bs_hi + BS_ELEMS;

    int tid = threadIdx.x;
    int wid = tid >> 5, lane = tid & 31;
    int wm = wid >> 2;        // 0..1
    int wn = wid & 3;         // 0..3
    int gr = lane >> 2;       // group id 0..7
    int tg = lane & 3;        // thread-in-group 0..3

    float acc[4][4][4];
#pragma unroll
    for (int i = 0; i < 4; i++)
#pragma unroll
        for (int j = 0; j < 4; j++)
#pragma unroll
            for (int r = 0; r < 4; r++) acc[i][j][r] = 0.f;

    int nchunks = K >> 5;
    for (int c = 0; c < nchunks; c++) {
        int kt = c << 5;
        // ---- stage A chunk: 128 rows x 32 cols, hi/lo tf32 ----
#pragma unroll
        for (int it = 0; it < 4; it++) {
            int idx = it * 1024 + tid * 4;
            int row = idx >> 5;
            int col = idx & 31;
            float4 v = *(const float4*)&A[(size_t)(row0 + row) * K + kt + col];
            if (relu) {
                v.x = fmaxf(v.x, 0.f); v.y = fmaxf(v.y, 0.f);
                v.z = fmaxf(v.z, 0.f); v.w = fmaxf(v.w, 0.f);
            }
            float h0 = tf32_val(v.x), h1 = tf32_val(v.y), h2 = tf32_val(v.z), h3 = tf32_val(v.w);
            int o = row * AS_STRIDE + col;
            As_hi[o + 0] = h0; As_hi[o + 1] = h1; As_hi[o + 2] = h2; As_hi[o + 3] = h3;
            As_lo[o + 0] = tf32_val(v.x - h0);
            As_lo[o + 1] = tf32_val(v.y - h1);
            As_lo[o + 2] = tf32_val(v.z - h2);
            As_lo[o + 3] = tf32_val(v.w - h3);
        }
        // ---- stage B chunk: 32 k-rows x 128 cols ----
#pragma unroll
        for (int it = 0; it < 4; it++) {
            int idx = it * 1024 + tid * 4;
            int kr = idx >> 7;
            int cc = idx & 127;
            float4 v = *(const float4*)&W[(size_t)(kt + kr) * Ntot + col0 + cc];
            float h0 = tf32_val(v.x), h1 = tf32_val(v.y), h2 = tf32_val(v.z), h3 = tf32_val(v.w);
            int o = kr * BS_STRIDE + cc;
            Bs_hi[o + 0] = h0; Bs_hi[o + 1] = h1; Bs_hi[o + 2] = h2; Bs_hi[o + 3] = h3;
            Bs_lo[o + 0] = tf32_val(v.x - h0);
            Bs_lo[o + 1] = tf32_val(v.y - h1);
            Bs_lo[o + 2] = tf32_val(v.z - h2);
            Bs_lo[o + 3] = tf32_val(v.w - h3);
        }
        __syncthreads();

#pragma unroll
        for (int ks = 0; ks < 4; ks++) {
            int k0 = ks * 8;
            uint32_t ah[4][4], al[4][4];
#pragma unroll
            for (int mt = 0; mt < 4; mt++) {
                int rbase = (wm * 64 + mt * 16 + gr) * AS_STRIDE + k0 + tg;
                ah[mt][0] = __float_as_uint(As_hi[rbase]);
                ah[mt][1] = __float_as_uint(As_hi[rbase + 8 * AS_STRIDE]);
                ah[mt][2] = __float_as_uint(As_hi[rbase + 4]);
                ah[mt][3] = __float_as_uint(As_hi[rbase + 8 * AS_STRIDE + 4]);
                al[mt][0] = __float_as_uint(As_lo[rbase]);
                al[mt][1] = __float_as_uint(As_lo[rbase + 8 * AS_STRIDE]);
                al[mt][2] = __float_as_uint(As_lo[rbase + 4]);
                al[mt][3] = __float_as_uint(As_lo[rbase + 8 * AS_STRIDE + 4]);
            }
            uint32_t bh[4][2], bl[4][2];
#pragma unroll
            for (int nt = 0; nt < 4; nt++) {
                int cbase = (k0 + tg) * BS_STRIDE + wn * 32 + nt * 8 + gr;
                bh[nt][0] = __float_as_uint(Bs_hi[cbase]);
                bh[nt][1] = __float_as_uint(Bs_hi[cbase + 4 * BS_STRIDE]);
                bl[nt][0] = __float_as_uint(Bs_lo[cbase]);
                bl[nt][1] = __float_as_uint(Bs_lo[cbase + 4 * BS_STRIDE]);
            }
#pragma unroll
            for (int mt = 0; mt < 4; mt++)
#pragma unroll
                for (int nt = 0; nt < 4; nt++) {
                    mma_tf32(acc[mt][nt], ah[mt], bh[nt]);
                    mma_tf32(acc[mt][nt], ah[mt], bl[nt]);
                    mma_tf32(acc[mt][nt], al[mt], bh[nt]);
                }
        }
        __syncthreads();
    }

    // ---- epilogue ----
#pragma unroll
    for (int mt = 0; mt < 4; mt++) {
#pragma unroll
        for (int nt = 0; nt < 4; nt++) {
            int row = row0 + wm * 64 + mt * 16 + gr;
            int col = col0 + wn * 32 + nt * 8 + 2 * tg;
            float b0 = 0.f, b1 = 0.f;
            if (bias) { b0 = bias[col]; b1 = bias[col + 1]; }
            float2 o0 = {acc[mt][nt][0] + b0, acc[mt][nt][1] + b1};
            float2 o1 = {acc[mt][nt][2] + b0, acc[mt][nt][3] + b1};
            *(float2*)&C[(size_t)row * Ntot + col] = o0;
            *(float2*)&C[(size_t)(row + 8) * Ntot + col] = o1;
        }
    }
}

// QKVS fused: blockIdx.y selects weights/bias/output, blockIdx.x = row tile
__global__ __launch_bounds__(256) void mma_gemm_qkvs(
    const float* __restrict__ A,
    const float* __restrict__ Wq, const float* __restrict__ bq, float* __restrict__ Cq,
    const float* __restrict__ Wk, const float* __restrict__ bk, float* __restrict__ Ck,
    const float* __restrict__ Wv, const float* __restrict__ bv, float* __restrict__ Cv,
    const float* __restrict__ Ws, const float* __restrict__ bs, float* __restrict__ Cs) {
    const float* W; const float* bias; float* C;
    switch (blockIdx.y) {
        case 0: W = Wq; bias = bq; C = Cq; break;
        case 1: W = Wk; bias = bk; C = Ck; break;
        case 2: W = Wv; bias = bv; C = Cv; break;
        default: W = Ws; bias = bs; C = Cs; break;
    }
    mma_gemm_body(A, W, bias, C, blockIdx.x * 128, E_, E_, 0, 0);
}

// generic: blockIdx.x = row tile, blockIdx.y = col tile
__global__ __launch_bounds__(256) void mma_gemm(
    const float* __restrict__ A, const float* __restrict__ W,
    float* __restrict__ C, int K, int Ntot, int relu) {
    mma_gemm_body(A, W, nullptr, C, blockIdx.x * 128, K, Ntot, blockIdx.y * 128, relu);
}

// ---------------- CSR build ----------------
__global__ void zero_deg_kernel() {
    int i = blockIdx.x * blockDim.x + threadIdx.x;
    if (i < NM_) g_deg_m[i] = 0;
    if (i < NO_) g_deg_o[i] = 0;
}

__global__ void count_kernel(const int* __restrict__ dst, int* __restrict__ deg, int ne) {
    int e = blockIdx.x * blockDim.x + threadIdx.x;
    if (e < ne) atomicAdd(&deg[dst[e]], 1);
}

__global__ void scan_local_kernel(const int* __restrict__ deg, int* __restrict__ off,
                                  int* __restrict__ bsum) {
    __shared__ int ws[8];
    int tid = threadIdx.x;
    int base = blockIdx.x * 1024 + tid * 4;
    int4 d = *(const int4*)&deg[base];
    int s = d.x + d.y + d.z + d.w;
    int lane = tid & 31, wid = tid >> 5;
    int v = s;
#pragma unroll
    for (int o = 1; o < 32; o <<= 1) {
        int t = __shfl_up_sync(0xffffffffu, v, o);
        if (lane >= o) v += t;
    }
    if (lane == 31) ws[wid] = v;
    __syncthreads();
    if (tid == 0) {
        int run = 0;
#pragma unroll
        for (int w = 0; w < 8; w++) { int t = ws[w]; ws[w] = run; run += t; }
    }
    __syncthreads();
    int excl = v - s + ws[wid];
    int4 o4;
    o4.x = excl;
    o4.y = excl + d.x;
    o4.z = o4.y + d.y;
    o4.w = o4.z + d.z;
    *(int4*)&off[base] = o4;
    if (tid == 255) bsum[blockIdx.x] = excl + s;
}

__global__ void scan_bsums_kernel(int* __restrict__ bsum, int nb, int* __restrict__ off, int n) {
    __shared__ int sh[128];
    int tid = threadIdx.x;
    int val = (tid < nb) ? bsum[tid] : 0;
    sh[tid] = val;
    __syncthreads();
    int acc = val;
    for (int o = 1; o < 128; o <<= 1) {
        int t = (tid >= o) ? sh[tid - o] : 0;
        __syncthreads();
        acc += t;
        sh[tid] = acc;
        __syncthreads();
    }
    if (tid < nb) bsum[tid] = acc - val;
    if (tid == 127) off[n] = sh[127];
}

__global__ void scan_add_kernel(int* __restrict__ off, int* __restrict__ pos,
                                const int* __restrict__ bsum, int n) {
    int i = blockIdx.x * blockDim.x + threadIdx.x;
    if (i < n) {
        int v = off[i] + bsum[i >> 10];
        off[i] = v;
        pos[i] = v;
    }
}

__global__ void scatter_kernel(const int* __restrict__ src, const int* __restrict__ dst,
                               int* __restrict__ pos, int* __restrict__ csr, int ne) {
    int e = blockIdx.x * blockDim.x + threadIdx.x;
    if (e < ne) {
        int t = dst[e];
        int slot = atomicAdd(&pos[t], 1);
        csr[slot] = src[e];
    }
}

__global__ void dinv_kernel() {
    int i = blockIdx.x * blockDim.x + threadIdx.x;
    if (i < NO_) g_dinv[i] = rsqrtf((float)(g_deg_o[i] + 1));
}

// ---------------- masked mean embedding pool ----------------
__global__ void masked_mean_kernel(const int* __restrict__ tok,
                                   const float* __restrict__ table,
                                   float* __restrict__ out, int L) {
    __shared__ int ts[64];
    int n = blockIdx.x;
    int d = threadIdx.x;
    if (d < L) ts[d] = tok[n * L + d];
    __syncthreads();
    float acc = 0.f;
    int cnt = 0;
    for (int j = 0; j < L; j++) {
        int t = ts[j];
        if (t != 0) { acc += table[t * E_ + d]; cnt++; }
    }
    out[(size_t)n * E_ + d] = acc / (float)(cnt > 1 ? cnt : 1);
}

// ---------------- fused transformer-conv attention (one warp per dst node) -------
__global__ void attn_kernel() {
    int warp = threadIdx.x >> 5, lane = threadIdx.x & 31;
    int t = blockIdx.x * 8 + warp;
    const float4* q4 = (const float4*)g_q;
    const float4* k4 = (const float4*)g_k;
    const float4* v4 = (const float4*)g_v;
    float4 qv = q4[(size_t)t * 32 + lane];
    float m = -1e30f, ss = 0.f;
    float4 acc = {0.f, 0.f, 0.f, 0.f};
    int beg = g_off_m[t], end = g_off_m[t + 1];
    for (int i = beg; i < end; i++) {
        int s = g_csr_m[i];
        float4 kv = k4[(size_t)s * 32 + lane];
        float p = qv.x * kv.x + qv.y * kv.y + qv.z * kv.z + qv.w * kv.w;
        p += __shfl_xor_sync(0xffffffffu, p, 1);
        p += __shfl_xor_sync(0xffffffffu, p, 2);
        float sc = p * 0.25f;
        float mn = fmaxf(m, sc);
        float scale = expf(m - mn);
        float w = expf(sc - mn);
        float4 vv = v4[(size_t)s * 32 + lane];
        ss = ss * scale + w;
        acc.x = acc.x * scale + w * vv.x;
        acc.y = acc.y * scale + w * vv.y;
        acc.z = acc.z * scale + w * vv.z;
        acc.w = acc.w * scale + w * vv.w;
        m = mn;
    }
    float inv = 1.f / (ss + 1e-16f);
    float4* h4 = (float4*)g_hidden;
    float4 h = h4[(size_t)t * 32 + lane];
    h.x += acc.x * inv; h.y += acc.y * inv;
    h.z += acc.z * inv; h.w += acc.w * inv;
    h4[(size_t)t * 32 + lane] = h;
}

// ---------------- global attention (segments of 8) ----------------
__global__ void gattn8_kernel(const float* __restrict__ Wg, const float* __restrict__ bg) {
    int warp = threadIdx.x >> 5;
    int lane = threadIdx.x & 31;
    int n = blockIdx.x * 8 + warp;
    const float4* x4 = (const float4*)g_hidden;
    float4 wg = ((const float4*)Wg)[lane];
    float bgv = bg[0];
    float4 xr[8];
    float g[8];
#pragma unroll
    for (int j = 0; j < 8; j++) {
        float4 xv = x4[(size_t)(n * 8 + j) * 32 + lane];
        xr[j] = xv;
        float p = xv.x * wg.x + xv.y * wg.y + xv.z * wg.z + xv.w * wg.w;
#pragma unroll
        for (int off = 16; off; off >>= 1) p += __shfl_xor_sync(0xffffffffu, p, off);
        g[j] = p + bgv;
    }
    float m = g[0];
#pragma unroll
    for (int j = 1; j < 8; j++) m = fmaxf(m, g[j]);
    float ej[8], s = 0.f;
#pragma unroll
    for (int j = 0; j < 8; j++) { ej[j] = expf(g[j] - m); s += ej[j]; }
    float inv = 1.f / (s + 1e-16f);
    float4 o = {0.f, 0.f, 0.f, 0.f};
#pragma unroll
    for (int j = 0; j < 8; j++) {
        float a = ej[j] * inv;
        o.x += a * xr[j].x; o.y += a * xr[j].y; o.z += a * xr[j].z; o.w += a * xr[j].w;
    }
    float4 st = ((const float4*)g_stmt)[(size_t)n * 32 + lane];
    float4 res = {(o.x + st.x) * 0.5f, (o.y + st.y) * 0.5f,
                  (o.z + st.z) * 0.5f, (o.w + st.w) * 0.5f};
    ((float4*)g_minifn)[(size_t)n * 32 + lane] = res;
}

// ---------------- GCN gather ----------------
__global__ void gcn_gather_kernel(const float* __restrict__ xw, const float* __restrict__ bias,
                                  float* __restrict__ out, int Mv4) {
    int warp = threadIdx.x >> 5, lane = threadIdx.x & 31;
    int t = blockIdx.x * 8 + warp;
    float di = g_dinv[t];
    int beg = g_off_o[t], end = g_off_o[t + 1];
    const float4* x4 = (const float4*)xw;
    for (int c = lane; c < Mv4; c += 32) {
        float4 a = x4[(size_t)t * Mv4 + c];
        float4 bv = ((const float4*)bias)[c];
        float d2 = di * di;
        float4 acc = {a.x * d2 + bv.x, a.y * d2 + bv.y, a.z * d2 + bv.z, a.w * d2 + bv.w};
        for (int i = beg; i < end; i++) {
            int s = g_csr_o[i];
            float nr = g_dinv[s] * di;
            float4 x = x4[(size_t)s * Mv4 + c];
            acc.x += nr * x.x; acc.y += nr * x.y;
            acc.z += nr * x.z; acc.w += nr * x.w;
        }
        ((float4*)out)[(size_t)t * Mv4 + c] = acc;
    }
}

// ---------------- global attention (segments of 40) ----------------
__global__ void gattn40_kernel(const float* __restrict__ Wg, const float* __restrict__ bg) {
    __shared__ float gate[40];
    __shared__ float alpha[40];
    __shared__ float ms[2];
    int b = blockIdx.x;
    int tid = threadIdx.x;
    int warp = tid >> 5, lane = tid & 31;
    float4 wg = ((const float4*)Wg)[lane];
    for (int j = warp; j < 40; j += 4) {
        float4 xv = ((const float4*)g_fs)[(size_t)(b * 40 + j) * 32 + lane];
        float p = xv.x * wg.x + xv.y * wg.y + xv.z * wg.z + xv.w * wg.w;
#pragma unroll
        for (int off = 16; off; off >>= 1) p += __shfl_xor_sync(0xffffffffu, p, off);
        if (lane == 0) gate[j] = p + bg[0];
    }
    __syncthreads();
    if (tid == 0) {
        float m = gate[0];
        for (int j = 1; j < 40; j++) m = fmaxf(m, gate[j]);
        float s = 0.f;
        for (int j = 0; j < 40; j++) s += expf(gate[j] - m);
        ms[0] = m; ms[1] = s;
    }
    __syncthreads();
    if (tid < 40) alpha[tid] = expf(gate[tid] - ms[0]) / (ms[1] + 1e-16f);
    __syncthreads();
    float acc = 0.f;
    for (int j = 0; j < 40; j++)
        acc += alpha[j] * g_fs[(size_t)(b * 40 + j) * E_ + tid];
    g_fn[(size_t)b * E_ + tid] = acc;
}

// ---------------- cosine ----------------
__global__ void cos_kernel(float* __restrict__ out) {
    int warp = threadIdx.x >> 5, lane = threadIdx.x & 31;
    int b = blockIdx.x * 8 + warp;
    float4 a4 = ((const float4*)g_fn)[(size_t)b * 32 + lane];
    float4 b4 = ((const float4*)g_hn)[(size_t)b * 32 + lane];
    float dt = a4.x * b4.x + a4.y * b4.y + a4.z * b4.z + a4.w * b4.w;
    float na = a4.x * a4.x + a4.y * a4.y + a4.z * a4.z + a4.w * a4.w;
    float nb = b4.x * b4.x + b4.y * b4.y + b4.z * b4.z + b4.w * b4.w;
#pragma unroll
    for (int off = 16; off; off >>= 1) {
        dt += __shfl_xor_sync(0xffffffffu, dt, off);
        na += __shfl_xor_sync(0xffffffffu, na, off);
        nb += __shfl_xor_sync(0xffffffffu, nb, off);
    }
    if (lane == 0)
        out[b] = dt / (fmaxf(sqrtf(na), 1e-8f) * fmaxf(sqrtf(nb), 1e-8f));
}

// ---------------- launch ----------------
extern "C" void kernel_launch(void* const* d_in, const int* in_sizes, int n_in,
                              void* d_out, int out_size) {
    const int* desc_tokens = (const int*)d_in[0];
    const int* x_tokens    = (const int*)d_in[1];
    const int* mini_tokens = (const int*)d_in[2];
    const int* src         = (const int*)d_in[3];
    const int* dst         = (const int*)d_in[4];
    const int* mini_src    = (const int*)d_in[5];
    const int* mini_dst    = (const int*)d_in[6];
    const float* desc_table  = (const float*)d_in[9];
    const float* code_table  = (const float*)d_in[10];
    const float* code_table2 = (const float*)d_in[11];
    const float* Wq = (const float*)d_in[12]; const float* bq = (const float*)d_in[13];
    const float* Wk = (const float*)d_in[14]; const float* bk = (const float*)d_in[15];
    const float* Wv = (const float*)d_in[16]; const float* bv = (const float*)d_in[17];
    const float* Wskip = (const float*)d_in[18]; const float* bskip = (const float*)d_in[19];
    const float* W2 = (const float*)d_in[20]; const float* b2 = (const float*)d_in[21];
    const float* W3 = (const float*)d_in[22]; const float* b3 = (const float*)d_in[23];
    const float* Wg = (const float*)d_in[24]; const float* bg = (const float*)d_in[25];
    float* out = (float*)d_out;

    float *p_mini, *p_q, *p_k, *p_v, *p_hidden, *p_hn, *p_stmt, *p_minifn;
    float *p_xw1, *p_gc1, *p_xw2, *p_fs;
    cudaGetSymbolAddress((void**)&p_mini, g_mini);
    cudaGetSymbolAddress((void**)&p_q, g_q);
    cudaGetSymbolAddress((void**)&p_k, g_k);
    cudaGetSymbolAddress((void**)&p_v, g_v);
    cudaGetSymbolAddress((void**)&p_hidden, g_hidden);
    cudaGetSymbolAddress((void**)&p_hn, g_hn);
    cudaGetSymbolAddress((void**)&p_stmt, g_stmt);
    cudaGetSymbolAddress((void**)&p_minifn, g_minifn);
    cudaGetSymbolAddress((void**)&p_xw1, g_xw1);
    cudaGetSymbolAddress((void**)&p_gc1, g_gc1);
    cudaGetSymbolAddress((void**)&p_xw2, g_xw2);
    cudaGetSymbolAddress((void**)&p_fs, g_fs);

    int *p_deg_m, *p_off_m, *p_pos_m, *p_csr_m, *p_bsum_m;
    int *p_deg_o, *p_off_o, *p_pos_o, *p_csr_o, *p_bsum_o;
    cudaGetSymbolAddress((void**)&p_deg_m, g_deg_m);
    cudaGetSymbolAddress((void**)&p_off_m, g_off_m);
    cudaGetSymbolAddress((void**)&p_pos_m, g_pos_m);
    cudaGetSymbolAddress((void**)&p_csr_m, g_csr_m);
    cudaGetSymbolAddress((void**)&p_bsum_m, g_bsum_m);
    cudaGetSymbolAddress((void**)&p_deg_o, g_deg_o);
    cudaGetSymbolAddress((void**)&p_off_o, g_off_o);
    cudaGetSymbolAddress((void**)&p_pos_o, g_pos_o);
    cudaGetSymbolAddress((void**)&p_csr_o, g_csr_o);
    cudaGetSymbolAddress((void**)&p_bsum_o, g_bsum_o);

    // opt-in dynamic smem for the mma GEMMs (69 KB)
    cudaFuncSetAttribute(mma_gemm_qkvs, cudaFuncAttributeMaxDynamicSharedMemorySize, MMA_SMEM);
    cudaFuncSetAttribute(mma_gemm, cudaFuncAttributeMaxDynamicSharedMemorySize, MMA_SMEM);

    // ---- CSR build ----
    zero_deg_kernel<<<(NM_ + 255) / 256, 256>>>();
    count_kernel<<<(EM_ + 255) / 256, 256>>>(mini_dst, p_deg_m, EM_);
    count_kernel<<<(EO_ + 255) / 256, 256>>>(dst, p_deg_o, EO_);
    scan_local_kernel<<<NM_ / 1024, 256>>>(p_deg_m, p_off_m, p_bsum_m);
    scan_local_kernel<<<NO_ / 1024, 256>>>(p_deg_o, p_off_o, p_bsum_o);
    scan_bsums_kernel<<<1, 128>>>(p_bsum_m, NM_ / 1024, p_off_m, NM_);
    scan_bsums_kernel<<<1, 128>>>(p_bsum_o, NO_ / 1024, p_off_o, NO_);
    scan_add_kernel<<<NM_ / 256, 256>>>(p_off_m, p_pos_m, p_bsum_m, NM_);
    scan_add_kernel<<<NO_ / 256, 256>>>(p_off_o, p_pos_o, p_bsum_o, NO_);
    dinv_kernel<<<(NO_ + 255) / 256, 256>>>();
    scatter_kernel<<<(EM_ + 255) / 256, 256>>>(mini_src, mini_dst, p_pos_m, p_csr_m, EM_);
    scatter_kernel<<<(EO_ + 255) / 256, 256>>>(src, dst, p_pos_o, p_csr_o, EO_);

    // ---- embeddings ----
    masked_mean_kernel<<<B_, E_>>>(desc_tokens, desc_table, p_hn, LD_);
    masked_mean_kernel<<<NO_, E_>>>(x_tokens, code_table2, p_stmt, LO_);
    masked_mean_kernel<<<NM_, E_>>>(mini_tokens, code_table, p_mini, LM_);

    // ---- fused q,k,v,skip projections (3xTF32 mma.sync) ----
    {
        dim3 grid(NM_ / 128, 4);
        mma_gemm_qkvs<<<grid, 256, MMA_SMEM>>>(p_mini,
                                               Wq, bq, p_q, Wk, bk, p_k,
                                               Wv, bv, p_v, Wskip, bskip, p_hidden);
    }

    // ---- fused attention ----
    attn_kernel<<<NM_ / 8, 256>>>();

    // ---- global attention (segments of 8) ----
    gattn8_kernel<<<NO_ / 8, 256>>>(Wg, bg);

    // ---- GCN layer 1: xw1 = minifn @ W2 ----
    {
        dim3 grid(NO_ / 128, HID_ / 128);
        mma_gemm<<<grid, 256, MMA_SMEM>>>(p_minifn, W2, p_xw1, E_, HID_, 0);
    }
    gcn_gather_kernel<<<NO_ / 8, 256>>>(p_xw1, b2, p_gc1, HID_ / 4);

    // ---- GCN layer 2: xw2 = relu(gc1) @ W3 ----
    {
        dim3 grid(NO_ / 128, E_ / 128);
        mma_gemm<<<grid, 256, MMA_SMEM>>>(p_gc1, W3, p_xw2, HID_, E_, 1);
    }
    gcn_gather_kernel<<<NO_ / 8, 256>>>(p_xw2, b3, p_fs, E_ / 4);

    // ---- readout ----
    gattn40_kernel<<<B_, E_>>>(Wg, bg);
    cos_kernel<<<B_ / 8, 256>>>(out);
    (void)in_sizes; (void)n_in; (void)out_size;
}

// round 6
// speedup vs baseline: 2.4997x; 1.1679x over previous
#include <cuda_runtime.h>
#include <cstdint>

#define B_   256
#define LD_  64
#define NO_  10240
#define LO_  32
#define NM_  81920
#define LM_  16
#define EO_  81920
#define EM_  327680
#define E_   128
#define HID_ 256
#define H_   8
#define Dh_  16

// ---------------- scratch ----------------
__device__ float g_hn[B_ * E_];
__device__ float g_stmt[NO_ * E_];
__device__ float g_mini[NM_ * E_];
__device__ float g_q[NM_ * E_];
__device__ float g_k[NM_ * E_];
__device__ float g_v[NM_ * E_];
__device__ float g_hidden[NM_ * E_];
__device__ float g_minifn[NO_ * E_];
__device__ float g_dinv[NO_];
__device__ float g_xw1[NO_ * HID_];
__device__ float g_gc1[NO_ * HID_];
__device__ float g_xw2[NO_ * E_];
__device__ float g_fs[NO_ * E_];
__device__ float g_fn[B_ * E_];

__device__ int g_deg_m[NM_];
__device__ int g_off_m[NM_ + 1];
__device__ int g_pos_m[NM_];
__device__ int g_csr_m[EM_];
__device__ int g_bsum_m[256];
__device__ int g_deg_o[NO_];
__device__ int g_off_o[NO_ + 1];
__device__ int g_pos_o[NO_];
__device__ int g_csr_o[EO_];
__device__ int g_bsum_o[256];

// ---------------- tf32 / mma helpers ----------------
__device__ __forceinline__ float tf32_val(float x) {
    float r;
    asm("cvt.rna.tf32.f32 %0, %1;" : "=f"(r) : "f"(x));
    return r;
}
__device__ __forceinline__ void mma_tf32(float* d, const uint32_t* a, const uint32_t* b) {
    asm volatile(
        "mma.sync.aligned.m16n8k8.row.col.f32.tf32.tf32.f32 "
        "{%0,%1,%2,%3}, {%4,%5,%6,%7}, {%8,%9}, {%0,%1,%2,%3};"
        : "+f"(d[0]), "+f"(d[1]), "+f"(d[2]), "+f"(d[3])
        : "r"(a[0]), "r"(a[1]), "r"(a[2]), "r"(a[3]), "r"(b[0]), "r"(b[1]));
}
__device__ __forceinline__ uint32_t smem_u32(const void* p) {
    uint32_t a;
    asm("{ .reg .u64 t; cvta.to.shared.u64 t, %1; cvt.u32.u64 %0, t; }" : "=r"(a) : "l"(p));
    return a;
}
__device__ __forceinline__ void cp16(uint32_t dst, const void* src) {
    asm volatile("cp.async.cg.shared.global [%0], [%1], 16;" :: "r"(dst), "l"(src));
}
__device__ __forceinline__ void cp_commit() {
    asm volatile("cp.async.commit_group;" ::: "memory");
}
template <int N>
__device__ __forceinline__ void cp_wait() {
    asm volatile("cp.async.wait_group %0;" :: "n"(N) : "memory");
}

// smem strides (floats): A 32+4 (lane-bijective banks), B 128+8 (tg*8+gr bijective)
#define AS_STRIDE 36
#define BS_STRIDE 136
#define AS_ELEMS (128 * AS_STRIDE)  // 4608 floats / stage
#define BS_ELEMS (32 * BS_STRIDE)   // 4352 floats / stage
#define MMA_SMEM ((2 * AS_ELEMS + 2 * BS_ELEMS) * 4)  // 71680 bytes

// ---------------- 3xTF32 mma.sync GEMM, cp.async double-buffered ----------------
// C[128 x 128] tile = A@W (+bias). A: [*,K] fp32 row-major; W: [K,Ntot]; K % 32 == 0.
// 256 threads = 8 warps (2 M x 4 N); warp tile 64x32; 4x4 m16n8k8; hi/lo split in regs.
template <bool RELU>
__device__ void mma_gemm_body(const float* __restrict__ A, const float* __restrict__ W,
                              const float* __restrict__ bias, float* __restrict__ C,
                              int row0, int K, int Ntot, int col0) {
    extern __shared__ __align__(16) float sm[];
    uint32_t sbase = smem_u32(sm);

    int tid = threadIdx.x;
    int wid = tid >> 5, lane = tid & 31;
    int wm = wid >> 2;        // 0..1
    int wn = wid & 3;         // 0..3
    int gr = lane >> 2;       // 0..7
    int tg = lane & 3;        // 0..3

    float acc[4][4][4];
#pragma unroll
    for (int i = 0; i < 4; i++)
#pragma unroll
        for (int j = 0; j < 4; j++)
#pragma unroll
            for (int r = 0; r < 4; r++) acc[i][j][r] = 0.f;

    int nch = K >> 5;

    // stage issue: copy A chunk (128x32) + B chunk (32x128) into buffer (c&1)
    auto issue = [&](int c) {
        int kt = c << 5;
        int buf = c & 1;
        uint32_t abase = sbase + (uint32_t)buf * AS_ELEMS * 4;
        uint32_t bbase = sbase + (uint32_t)(2 * AS_ELEMS + buf * BS_ELEMS) * 4;
#pragma unroll
        for (int it = 0; it < 4; it++) {
            int idx = it * 256 + tid;
            int row = idx >> 3;
            int cc = (idx & 7) * 4;
            cp16(abase + (uint32_t)(row * AS_STRIDE + cc) * 4,
                 &A[(size_t)(row0 + row) * K + kt + cc]);
        }
#pragma unroll
        for (int it = 0; it < 4; it++) {
            int idx = it * 256 + tid;
            int kr = idx >> 5;
            int cc = (idx & 31) * 4;
            cp16(bbase + (uint32_t)(kr * BS_STRIDE + cc) * 4,
                 &W[(size_t)(kt + kr) * Ntot + col0 + cc]);
        }
        cp_commit();
    };

    issue(0);
    for (int c = 0; c < nch; c++) {
        if (c + 1 < nch) { issue(c + 1); cp_wait<1>(); }
        else             { cp_wait<0>(); }
        __syncthreads();

        const float* As = sm + (c & 1) * AS_ELEMS;
        const float* Bs = sm + 2 * AS_ELEMS + (c & 1) * BS_ELEMS;

#pragma unroll
        for (int ks = 0; ks < 4; ks++) {
            int k0 = ks * 8;
            uint32_t ah[4][4], al[4][4];
#pragma unroll
            for (int mt = 0; mt < 4; mt++) {
                int rbase = (wm * 64 + mt * 16 + gr) * AS_STRIDE + k0 + tg;
                float r0 = As[rbase];
                float r1 = As[rbase + 8 * AS_STRIDE];
                float r2 = As[rbase + 4];
                float r3 = As[rbase + 8 * AS_STRIDE + 4];
                if (RELU) {
                    r0 = fmaxf(r0, 0.f); r1 = fmaxf(r1, 0.f);
                    r2 = fmaxf(r2, 0.f); r3 = fmaxf(r3, 0.f);
                }
                float h0 = tf32_val(r0), h1 = tf32_val(r1), h2 = tf32_val(r2), h3 = tf32_val(r3);
                ah[mt][0] = __float_as_uint(h0);
                ah[mt][1] = __float_as_uint(h1);
                ah[mt][2] = __float_as_uint(h2);
                ah[mt][3] = __float_as_uint(h3);
                al[mt][0] = __float_as_uint(tf32_val(r0 - h0));
                al[mt][1] = __float_as_uint(tf32_val(r1 - h1));
                al[mt][2] = __float_as_uint(tf32_val(r2 - h2));
                al[mt][3] = __float_as_uint(tf32_val(r3 - h3));
            }
            uint32_t bh[4][2], bl[4][2];
#pragma unroll
            for (int nt = 0; nt < 4; nt++) {
                int cbase = (k0 + tg) * BS_STRIDE + wn * 32 + nt * 8 + gr;
                float s0 = Bs[cbase];
                float s1 = Bs[cbase + 4 * BS_STRIDE];
                float h0 = tf32_val(s0), h1 = tf32_val(s1);
                bh[nt][0] = __float_as_uint(h0);
                bh[nt][1] = __float_as_uint(h1);
                bl[nt][0] = __float_as_uint(tf32_val(s0 - h0));
                bl[nt][1] = __float_as_uint(tf32_val(s1 - h1));
            }
#pragma unroll
            for (int mt = 0; mt < 4; mt++)
#pragma unroll
                for (int nt = 0; nt < 4; nt++) {
                    mma_tf32(acc[mt][nt], ah[mt], bh[nt]);
                    mma_tf32(acc[mt][nt], ah[mt], bl[nt]);
                    mma_tf32(acc[mt][nt], al[mt], bh[nt]);
                }
        }
        __syncthreads();
    }

    // ---- epilogue ----
#pragma unroll
    for (int mt = 0; mt < 4; mt++) {
#pragma unroll
        for (int nt = 0; nt < 4; nt++) {
            int row = row0 + wm * 64 + mt * 16 + gr;
            int col = col0 + wn * 32 + nt * 8 + 2 * tg;
            float b0 = 0.f, b1 = 0.f;
            if (bias) { b0 = bias[col]; b1 = bias[col + 1]; }
            float2 o0 = {acc[mt][nt][0] + b0, acc[mt][nt][1] + b1};
            float2 o1 = {acc[mt][nt][2] + b0, acc[mt][nt][3] + b1};
            *(float2*)&C[(size_t)row * Ntot + col] = o0;
            *(float2*)&C[(size_t)(row + 8) * Ntot + col] = o1;
        }
    }
}

// QKVS fused: blockIdx.y selects weights/bias/output, blockIdx.x = row tile
__global__ __launch_bounds__(256) void mma_gemm_qkvs(
    const float* __restrict__ A,
    const float* __restrict__ Wq, const float* __restrict__ bq, float* __restrict__ Cq,
    const float* __restrict__ Wk, const float* __restrict__ bk, float* __restrict__ Ck,
    const float* __restrict__ Wv, const float* __restrict__ bv, float* __restrict__ Cv,
    const float* __restrict__ Ws, const float* __restrict__ bs, float* __restrict__ Cs) {
    const float* W; const float* bias; float* C;
    switch (blockIdx.y) {
        case 0: W = Wq; bias = bq; C = Cq; break;
        case 1: W = Wk; bias = bk; C = Ck; break;
        case 2: W = Wv; bias = bv; C = Cv; break;
        default: W = Ws; bias = bs; C = Cs; break;
    }
    mma_gemm_body<false>(A, W, bias, C, blockIdx.x * 128, E_, E_, 0);
}

__global__ __launch_bounds__(256) void mma_gemm_plain(
    const float* __restrict__ A, const float* __restrict__ W,
    float* __restrict__ C, int K, int Ntot) {
    mma_gemm_body<false>(A, W, nullptr, C, blockIdx.x * 128, K, Ntot, blockIdx.y * 128);
}
__global__ __launch_bounds__(256) void mma_gemm_relu(
    const float* __restrict__ A, const float* __restrict__ W,
    float* __restrict__ C, int K, int Ntot) {
    mma_gemm_body<true>(A, W, nullptr, C, blockIdx.x * 128, K, Ntot, blockIdx.y * 128);
}

// ---------------- CSR build ----------------
__global__ void zero_deg_kernel() {
    int i = blockIdx.x * blockDim.x + threadIdx.x;
    if (i < NM_) g_deg_m[i] = 0;
    if (i < NO_) g_deg_o[i] = 0;
}

__global__ void count_kernel(const int* __restrict__ dst, int* __restrict__ deg, int ne) {
    int e = blockIdx.x * blockDim.x + threadIdx.x;
    if (e < ne) atomicAdd(&deg[dst[e]], 1);
}

__global__ void scan_local_kernel(const int* __restrict__ deg, int* __restrict__ off,
                                  int* __restrict__ bsum) {
    __shared__ int ws[8];
    int tid = threadIdx.x;
    int base = blockIdx.x * 1024 + tid * 4;
    int4 d = *(const int4*)&deg[base];
    int s = d.x + d.y + d.z + d.w;
    int lane = tid & 31, wid = tid >> 5;
    int v = s;
#pragma unroll
    for (int o = 1; o < 32; o <<= 1) {
        int t = __shfl_up_sync(0xffffffffu, v, o);
        if (lane >= o) v += t;
    }
    if (lane == 31) ws[wid] = v;
    __syncthreads();
    if (tid == 0) {
        int run = 0;
#pragma unroll
        for (int w = 0; w < 8; w++) { int t = ws[w]; ws[w] = run; run += t; }
    }
    __syncthreads();
    int excl = v - s + ws[wid];
    int4 o4;
    o4.x = excl;
    o4.y = excl + d.x;
    o4.z = o4.y + d.y;
    o4.w = o4.z + d.z;
    *(int4*)&off[base] = o4;
    if (tid == 255) bsum[blockIdx.x] = excl + s;
}

__global__ void scan_bsums_kernel(int* __restrict__ bsum, int nb, int* __restrict__ off, int n) {
    __shared__ int sh[128];
    int tid = threadIdx.x;
    int val = (tid < nb) ? bsum[tid] : 0;
    sh[tid] = val;
    __syncthreads();
    int acc = val;
    for (int o = 1; o < 128; o <<= 1) {
        int t = (tid >= o) ? sh[tid - o] : 0;
        __syncthreads();
        acc += t;
        sh[tid] = acc;
        __syncthreads();
    }
    if (tid < nb) bsum[tid] = acc - val;
    if (tid == 127) off[n] = sh[127];
}

__global__ void scan_add_kernel(int* __restrict__ off, int* __restrict__ pos,
                                const int* __restrict__ bsum, int n) {
    int i = blockIdx.x * blockDim.x + threadIdx.x;
    if (i < n) {
        int v = off[i] + bsum[i >> 10];
        off[i] = v;
        pos[i] = v;
    }
}

__global__ void scatter_kernel(const int* __restrict__ src, const int* __restrict__ dst,
                               int* __restrict__ pos, int* __restrict__ csr, int ne) {
    int e = blockIdx.x * blockDim.x + threadIdx.x;
    if (e < ne) {
        int t = dst[e];
        int slot = atomicAdd(&pos[t], 1);
        csr[slot] = src[e];
    }
}

__global__ void dinv_kernel() {
    int i = blockIdx.x * blockDim.x + threadIdx.x;
    if (i < NO_) g_dinv[i] = rsqrtf((float)(g_deg_o[i] + 1));
}

// ---------------- masked mean embedding pool (float4, 4 nodes/block) -------------
__global__ void masked_mean4_kernel(const int* __restrict__ tok,
                                    const float* __restrict__ table,
                                    float* __restrict__ out, int L) {
    __shared__ int ts[4][64];
    int warp = threadIdx.x >> 5, lane = threadIdx.x & 31;
    int n = blockIdx.x * 4 + warp;
    for (int j = lane; j < L; j += 32) ts[warp][j] = tok[n * L + j];
    __syncwarp();
    const float4* t4 = (const float4*)table;
    float4 acc = {0.f, 0.f, 0.f, 0.f};
    int cnt = 0;
    for (int j = 0; j < L; j++) {
        int t = ts[warp][j];
        if (t != 0) {
            float4 e = t4[(size_t)t * 32 + lane];
            acc.x += e.x; acc.y += e.y; acc.z += e.z; acc.w += e.w;
            cnt++;
        }
    }
    float inv = 1.f / (float)(cnt > 1 ? cnt : 1);
    float4 o = {acc.x * inv, acc.y * inv, acc.z * inv, acc.w * inv};
    ((float4*)out)[(size_t)n * 32 + lane] = o;
}

// ---------------- fused transformer-conv attention (one warp per dst node) -------
__global__ void attn_kernel() {
    int warp = threadIdx.x >> 5, lane = threadIdx.x & 31;
    int t = blockIdx.x * 8 + warp;
    const float4* q4 = (const float4*)g_q;
    const float4* k4 = (const float4*)g_k;
    const float4* v4 = (const float4*)g_v;
    float4 qv = q4[(size_t)t * 32 + lane];
    float m = -1e30f, ss = 0.f;
    float4 acc = {0.f, 0.f, 0.f, 0.f};
    int beg = g_off_m[t], end = g_off_m[t + 1];
    for (int i = beg; i < end; i++) {
        int s = g_csr_m[i];
        float4 kv = k4[(size_t)s * 32 + lane];
        float p = qv.x * kv.x + qv.y * kv.y + qv.z * kv.z + qv.w * kv.w;
        p += __shfl_xor_sync(0xffffffffu, p, 1);
        p += __shfl_xor_sync(0xffffffffu, p, 2);
        float sc = p * 0.25f;
        float mn = fmaxf(m, sc);
        float scale = __expf(m - mn);
        float w = __expf(sc - mn);
        float4 vv = v4[(size_t)s * 32 + lane];
        ss = ss * scale + w;
        acc.x = acc.x * scale + w * vv.x;
        acc.y = acc.y * scale + w * vv.y;
        acc.z = acc.z * scale + w * vv.z;
        acc.w = acc.w * scale + w * vv.w;
        m = mn;
    }
    float inv = 1.f / (ss + 1e-16f);
    float4* h4 = (float4*)g_hidden;
    float4 h = h4[(size_t)t * 32 + lane];
    h.x += acc.x * inv; h.y += acc.y * inv;
    h.z += acc.z * inv; h.w += acc.w * inv;
    h4[(size_t)t * 32 + lane] = h;
}

// ---------------- global attention (segments of 8) ----------------
__global__ void gattn8_kernel(const float* __restrict__ Wg, const float* __restrict__ bg) {
    int warp = threadIdx.x >> 5;
    int lane = threadIdx.x & 31;
    int n = blockIdx.x * 8 + warp;
    const float4* x4 = (const float4*)g_hidden;
    float4 wg = ((const float4*)Wg)[lane];
    float bgv = bg[0];
    float4 xr[8];
    float g[8];
#pragma unroll
    for (int j = 0; j < 8; j++) {
        float4 xv = x4[(size_t)(n * 8 + j) * 32 + lane];
        xr[j] = xv;
        float p = xv.x * wg.x + xv.y * wg.y + xv.z * wg.z + xv.w * wg.w;
#pragma unroll
        for (int off = 16; off; off >>= 1) p += __shfl_xor_sync(0xffffffffu, p, off);
        g[j] = p + bgv;
    }
    float m = g[0];
#pragma unroll
    for (int j = 1; j < 8; j++) m = fmaxf(m, g[j]);
    float ej[8], s = 0.f;
#pragma unroll
    for (int j = 0; j < 8; j++) { ej[j] = __expf(g[j] - m); s += ej[j]; }
    float inv = 1.f / (s + 1e-16f);
    float4 o = {0.f, 0.f, 0.f, 0.f};
#pragma unroll
    for (int j = 0; j < 8; j++) {
        float a = ej[j] * inv;
        o.x += a * xr[j].x; o.y += a * xr[j].y; o.z += a * xr[j].z; o.w += a * xr[j].w;
    }
    float4 st = ((const float4*)g_stmt)[(size_t)n * 32 + lane];
    float4 res = {(o.x + st.x) * 0.5f, (o.y + st.y) * 0.5f,
                  (o.z + st.z) * 0.5f, (o.w + st.w) * 0.5f};
    ((float4*)g_minifn)[(size_t)n * 32 + lane] = res;
}

// ---------------- GCN gather ----------------
__global__ void gcn_gather_kernel(const float* __restrict__ xw, const float* __restrict__ bias,
                                  float* __restrict__ out, int Mv4) {
    int warp = threadIdx.x >> 5, lane = threadIdx.x & 31;
    int t = blockIdx.x * 8 + warp;
    float di = g_dinv[t];
    int beg = g_off_o[t], end = g_off_o[t + 1];
    const float4* x4 = (const float4*)xw;
    for (int c = lane; c < Mv4; c += 32) {
        float4 a = x4[(size_t)t * Mv4 + c];
        float4 bv = ((const float4*)bias)[c];
        float d2 = di * di;
        float4 acc = {a.x * d2 + bv.x, a.y * d2 + bv.y, a.z * d2 + bv.z, a.w * d2 + bv.w};
        for (int i = beg; i < end; i++) {
            int s = g_csr_o[i];
            float nr = g_dinv[s] * di;
            float4 x = x4[(size_t)s * Mv4 + c];
            acc.x += nr * x.x; acc.y += nr * x.y;
            acc.z += nr * x.z; acc.w += nr * x.w;
        }
        ((float4*)out)[(size_t)t * Mv4 + c] = acc;
    }
}

// ---------------- global attention (segments of 40) ----------------
__global__ void gattn40_kernel(const float* __restrict__ Wg, const float* __restrict__ bg) {
    __shared__ float gate[40];
    __shared__ float alpha[40];
    __shared__ float ms[2];
    int b = blockIdx.x;
    int tid = threadIdx.x;
    int warp = tid >> 5, lane = tid & 31;
    float4 wg = ((const float4*)Wg)[lane];
    for (int j = warp; j < 40; j += 4) {
        float4 xv = ((const float4*)g_fs)[(size_t)(b * 40 + j) * 32 + lane];
        float p = xv.x * wg.x + xv.y * wg.y + xv.z * wg.z + xv.w * wg.w;
#pragma unroll
        for (int off = 16; off; off >>= 1) p += __shfl_xor_sync(0xffffffffu, p, off);
        if (lane == 0) gate[j] = p + bg[0];
    }
    __syncthreads();
    if (tid == 0) {
        float m = gate[0];
        for (int j = 1; j < 40; j++) m = fmaxf(m, gate[j]);
        float s = 0.f;
        for (int j = 0; j < 40; j++) s += __expf(gate[j] - m);
        ms[0] = m; ms[1] = s;
    }
    __syncthreads();
    if (tid < 40) alpha[tid] = __expf(gate[tid] - ms[0]) / (ms[1] + 1e-16f);
    __syncthreads();
    float acc = 0.f;
    for (int j = 0; j < 40; j++)
        acc += alpha[j] * g_fs[(size_t)(b * 40 + j) * E_ + tid];
    g_fn[(size_t)b * E_ + tid] = acc;
}

// ---------------- cosine ----------------
__global__ void cos_kernel(float* __restrict__ out) {
    int warp = threadIdx.x >> 5, lane = threadIdx.x & 31;
    int b = blockIdx.x * 8 + warp;
    float4 a4 = ((const float4*)g_fn)[(size_t)b * 32 + lane];
    float4 b4 = ((const float4*)g_hn)[(size_t)b * 32 + lane];
    float dt = a4.x * b4.x + a4.y * b4.y + a4.z * b4.z + a4.w * b4.w;
    float na = a4.x * a4.x + a4.y * a4.y + a4.z * a4.z + a4.w * a4.w;
    float nb = b4.x * b4.x + b4.y * b4.y + b4.z * b4.z + b4.w * b4.w;
#pragma unroll
    for (int off = 16; off; off >>= 1) {
        dt += __shfl_xor_sync(0xffffffffu, dt, off);
        na += __shfl_xor_sync(0xffffffffu, na, off);
        nb += __shfl_xor_sync(0xffffffffu, nb, off);
    }
    if (lane == 0)
        out[b] = dt / (fmaxf(sqrtf(na), 1e-8f) * fmaxf(sqrtf(nb), 1e-8f));
}

// ---------------- launch ----------------
extern "C" void kernel_launch(void* const* d_in, const int* in_sizes, int n_in,
                              void* d_out, int out_size) {
    const int* desc_tokens = (const int*)d_in[0];
    const int* x_tokens    = (const int*)d_in[1];
    const int* mini_tokens = (const int*)d_in[2];
    const int* src         = (const int*)d_in[3];
    const int* dst         = (const int*)d_in[4];
    const int* mini_src    = (const int*)d_in[5];
    const int* mini_dst    = (const int*)d_in[6];
    const float* desc_table  = (const float*)d_in[9];
    const float* code_table  = (const float*)d_in[10];
    const float* code_table2 = (const float*)d_in[11];
    const float* Wq = (const float*)d_in[12]; const float* bq = (const float*)d_in[13];
    const float* Wk = (const float*)d_in[14]; const float* bk = (const float*)d_in[15];
    const float* Wv = (const float*)d_in[16]; const float* bv = (const float*)d_in[17];
    const float* Wskip = (const float*)d_in[18]; const float* bskip = (const float*)d_in[19];
    const float* W2 = (const float*)d_in[20]; const float* b2 = (const float*)d_in[21];
    const float* W3 = (const float*)d_in[22]; const float* b3 = (const float*)d_in[23];
    const float* Wg = (const float*)d_in[24]; const float* bg = (const float*)d_in[25];
    float* out = (float*)d_out;

    float *p_mini, *p_q, *p_k, *p_v, *p_hidden, *p_hn, *p_stmt, *p_minifn;
    float *p_xw1, *p_gc1, *p_xw2, *p_fs;
    cudaGetSymbolAddress((void**)&p_mini, g_mini);
    cudaGetSymbolAddress((void**)&p_q, g_q);
    cudaGetSymbolAddress((void**)&p_k, g_k);
    cudaGetSymbolAddress((void**)&p_v, g_v);
    cudaGetSymbolAddress((void**)&p_hidden, g_hidden);
    cudaGetSymbolAddress((void**)&p_hn, g_hn);
    cudaGetSymbolAddress((void**)&p_stmt, g_stmt);
    cudaGetSymbolAddress((void**)&p_minifn, g_minifn);
    cudaGetSymbolAddress((void**)&p_xw1, g_xw1);
    cudaGetSymbolAddress((void**)&p_gc1, g_gc1);
    cudaGetSymbolAddress((void**)&p_xw2, g_xw2);
    cudaGetSymbolAddress((void**)&p_fs, g_fs);

    int *p_deg_m, *p_off_m, *p_pos_m, *p_csr_m, *p_bsum_m;
    int *p_deg_o, *p_off_o, *p_pos_o, *p_csr_o, *p_bsum_o;
    cudaGetSymbolAddress((void**)&p_deg_m, g_deg_m);
    cudaGetSymbolAddress((void**)&p_off_m, g_off_m);
    cudaGetSymbolAddress((void**)&p_pos_m, g_pos_m);
    cudaGetSymbolAddress((void**)&p_csr_m, g_csr_m);
    cudaGetSymbolAddress((void**)&p_bsum_m, g_bsum_m);
    cudaGetSymbolAddress((void**)&p_deg_o, g_deg_o);
    cudaGetSymbolAddress((void**)&p_off_o, g_off_o);
    cudaGetSymbolAddress((void**)&p_pos_o, g_pos_o);
    cudaGetSymbolAddress((void**)&p_csr_o, g_csr_o);
    cudaGetSymbolAddress((void**)&p_bsum_o, g_bsum_o);

    cudaFuncSetAttribute(mma_gemm_qkvs, cudaFuncAttributeMaxDynamicSharedMemorySize, MMA_SMEM);
    cudaFuncSetAttribute(mma_gemm_plain, cudaFuncAttributeMaxDynamicSharedMemorySize, MMA_SMEM);
    cudaFuncSetAttribute(mma_gemm_relu, cudaFuncAttributeMaxDynamicSharedMemorySize, MMA_SMEM);

    // ---- CSR build ----
    zero_deg_kernel<<<(NM_ + 255) / 256, 256>>>();
    count_kernel<<<(EM_ + 255) / 256, 256>>>(mini_dst, p_deg_m, EM_);
    count_kernel<<<(EO_ + 255) / 256, 256>>>(dst, p_deg_o, EO_);
    scan_local_kernel<<<NM_ / 1024, 256>>>(p_deg_m, p_off_m, p_bsum_m);
    scan_local_kernel<<<NO_ / 1024, 256>>>(p_deg_o, p_off_o, p_bsum_o);
    scan_bsums_kernel<<<1, 128>>>(p_bsum_m, NM_ / 1024, p_off_m, NM_);
    scan_bsums_kernel<<<1, 128>>>(p_bsum_o, NO_ / 1024, p_off_o, NO_);
    scan_add_kernel<<<NM_ / 256, 256>>>(p_off_m, p_pos_m, p_bsum_m, NM_);
    scan_add_kernel<<<NO_ / 256, 256>>>(p_off_o, p_pos_o, p_bsum_o, NO_);
    dinv_kernel<<<(NO_ + 255) / 256, 256>>>();
    scatter_kernel<<<(EM_ + 255) / 256, 256>>>(mini_src, mini_dst, p_pos_m, p_csr_m, EM_);
    scatter_kernel<<<(EO_ + 255) / 256, 256>>>(src, dst, p_pos_o, p_csr_o, EO_);

    // ---- embeddings ----
    masked_mean4_kernel<<<B_ / 4, 128>>>(desc_tokens, desc_table, p_hn, LD_);
    masked_mean4_kernel<<<NO_ / 4, 128>>>(x_tokens, code_table2, p_stmt, LO_);
    masked_mean4_kernel<<<NM_ / 4, 128>>>(mini_tokens, code_table, p_mini, LM_);

    // ---- fused q,k,v,skip projections (3xTF32 mma.sync, cp.async pipelined) ----
    {
        dim3 grid(NM_ / 128, 4);
        mma_gemm_qkvs<<<grid, 256, MMA_SMEM>>>(p_mini,
                                               Wq, bq, p_q, Wk, bk, p_k,
                                               Wv, bv, p_v, Wskip, bskip, p_hidden);
    }

    // ---- fused attention ----
    attn_kernel<<<NM_ / 8, 256>>>();

    // ---- global attention (segments of 8) ----
    gattn8_kernel<<<NO_ / 8, 256>>>(Wg, bg);

    // ---- GCN layer 1: xw1 = minifn @ W2 ----
    {
        dim3 grid(NO_ / 128, HID_ / 128);
        mma_gemm_plain<<<grid, 256, MMA_SMEM>>>(p_minifn, W2, p_xw1, E_, HID_);
    }
    gcn_gather_kernel<<<NO_ / 8, 256>>>(p_xw1, b2, p_gc1, HID_ / 4);

    // ---- GCN layer 2: xw2 = relu(gc1) @ W3 ----
    {
        dim3 grid(NO_ / 128, E_ / 128);
        mma_gemm_relu<<<grid, 256, MMA_SMEM>>>(p_gc1, W3, p_xw2, HID_, E_);
    }
    gcn_gather_kernel<<<NO_ / 8, 256>>>(p_xw2, b3, p_fs, E_ / 4);

    // ---- readout ----
    gattn40_kernel<<<B_, E_>>>(Wg, bg);
    cos_kernel<<<B_ / 8, 256>>>(out);
    (void)in_sizes; (void)n_in; (void)out_size;
}

// round 7
// speedup vs baseline: 2.9768x; 1.1908x over previous
#include <cuda_runtime.h>
#include <cuda_bf16.h>
#include <cstdint>

#define B_   256
#define LD_  64
#define NO_  10240
#define LO_  32
#define NM_  81920
#define LM_  16
#define EO_  81920
#define EM_  327680
#define E_   128
#define HID_ 256
#define H_   8
#define Dh_  16

// ---------------- scratch ----------------
__device__ float g_hn[B_ * E_];
__device__ float g_stmt[NO_ * E_];
__device__ float g_q[NM_ * E_];
__device__ float g_k[NM_ * E_];
__device__ float g_v[NM_ * E_];
__device__ float g_hidden[NM_ * E_];
__device__ float g_dinv[NO_];
__device__ float g_xw1[NO_ * HID_];
__device__ float g_xw2[NO_ * E_];
__device__ float g_fs[NO_ * E_];
__device__ float g_fn[B_ * E_];

// bf16 split operand buffers (A matrices + transposed weights)
__device__ __align__(16) __nv_bfloat16 g_mini_hi[NM_ * E_], g_mini_lo[NM_ * E_];
__device__ __align__(16) __nv_bfloat16 g_mfn_hi[NO_ * E_],  g_mfn_lo[NO_ * E_];
__device__ __align__(16) __nv_bfloat16 g_gc1_hi[NO_ * HID_], g_gc1_lo[NO_ * HID_];
__device__ __align__(16) __nv_bfloat16 g_wtq_hi[E_ * E_], g_wtq_lo[E_ * E_];
__device__ __align__(16) __nv_bfloat16 g_wtk_hi[E_ * E_], g_wtk_lo[E_ * E_];
__device__ __align__(16) __nv_bfloat16 g_wtv_hi[E_ * E_], g_wtv_lo[E_ * E_];
__device__ __align__(16) __nv_bfloat16 g_wts_hi[E_ * E_], g_wts_lo[E_ * E_];
__device__ __align__(16) __nv_bfloat16 g_w2t_hi[HID_ * E_], g_w2t_lo[HID_ * E_];
__device__ __align__(16) __nv_bfloat16 g_w3t_hi[E_ * HID_], g_w3t_lo[E_ * HID_];

__device__ int g_deg_m[NM_];
__device__ int g_off_m[NM_ + 1];
__device__ int g_pos_m[NM_];
__device__ int g_csr_m[EM_];
__device__ int g_bsum_m[256];
__device__ int g_deg_o[NO_];
__device__ int g_off_o[NO_ + 1];
__device__ int g_pos_o[NO_];
__device__ int g_csr_o[EO_];
__device__ int g_bsum_o[256];

// ---------------- helpers ----------------
__device__ __forceinline__ uint32_t smem_u32(const void* p) {
    uint32_t a;
    asm("{ .reg .u64 t; cvta.to.shared.u64 t, %1; cvt.u32.u64 %0, t; }" : "=r"(a) : "l"(p));
    return a;
}
__device__ __forceinline__ void cp16(uint32_t dst, const void* src) {
    asm volatile("cp.async.cg.shared.global [%0], [%1], 16;" :: "r"(dst), "l"(src));
}
__device__ __forceinline__ void cp_commit() {
    asm volatile("cp.async.commit_group;" ::: "memory");
}
template <int N>
__device__ __forceinline__ void cp_wait() {
    asm volatile("cp.async.wait_group %0;" :: "n"(N) : "memory");
}
__device__ __forceinline__ void mma_bf16(float* d, const uint32_t* a, const uint32_t* b) {
    asm volatile(
        "mma.sync.aligned.m16n8k16.row.col.f32.bf16.bf16.f32 "
        "{%0,%1,%2,%3}, {%4,%5,%6,%7}, {%8,%9}, {%0,%1,%2,%3};"
        : "+f"(d[0]), "+f"(d[1]), "+f"(d[2]), "+f"(d[3])
        : "r"(a[0]), "r"(a[1]), "r"(a[2]), "r"(a[3]), "r"(b[0]), "r"(b[1]));
}

// split a float4 into bf16 hi/lo, store 4 consecutive elements at base
__device__ __forceinline__ void split_store4(__nv_bfloat16* hi, __nv_bfloat16* lo,
                                             size_t base, float4 v) {
    __nv_bfloat162 h0 = __floats2bfloat162_rn(v.x, v.y);
    __nv_bfloat162 h1 = __floats2bfloat162_rn(v.z, v.w);
    float rx = __bfloat162float(h0.x), ry = __bfloat162float(h0.y);
    float rz = __bfloat162float(h1.x), rw = __bfloat162float(h1.y);
    __nv_bfloat162 l0 = __floats2bfloat162_rn(v.x - rx, v.y - ry);
    __nv_bfloat162 l1 = __floats2bfloat162_rn(v.z - rz, v.w - rw);
    uint2 hp = {*(uint32_t*)&h0, *(uint32_t*)&h1};
    uint2 lp = {*(uint32_t*)&l0, *(uint32_t*)&l1};
    *(uint2*)(hi + base) = hp;
    *(uint2*)(lo + base) = lp;
}

// ---------------- weight transpose + split: out[n*K+k] = split(W[k*N+n]) ---------
__global__ void wsplit_kernel(const float* __restrict__ W, __nv_bfloat16* __restrict__ hi,
                              __nv_bfloat16* __restrict__ lo, int K, int N) {
    int i = blockIdx.x * blockDim.x + threadIdx.x;
    if (i >= K * N) return;
    int n = i / K, k = i - n * K;
    float v = W[(size_t)k * N + n];
    __nv_bfloat16 h = __float2bfloat16(v);
    hi[i] = h;
    lo[i] = __float2bfloat16(v - __bfloat162float(h));
}

// ---------------- bf16x3 mma.sync GEMM, cp.async double-buffered -----------------
// C[128x128] = A@W (+bias); A pre-split bf16 hi/lo [*,K] row-major;
// B pre-split + transposed [Ntot][K]. K % 32 == 0.
// 256 threads = 8 warps (2M x 4N); warp tile 64x32; m16n8k16.
#define GSTR 40                        // bf16 stride (bank-bijective for 32-bit LDS)
#define GST_ELEMS (128 * GSTR)         // 5120 bf16 per array
#define STAGE_ELEMS (4 * GST_ELEMS)    // Ahi,Alo,Bhi,Blo
#define GEMM_SMEM (2 * STAGE_ELEMS * 2)  // 81920 bytes

__device__ void bf16_gemm_body(const __nv_bfloat16* __restrict__ Ahi,
                               const __nv_bfloat16* __restrict__ Alo,
                               const __nv_bfloat16* __restrict__ Bhi,
                               const __nv_bfloat16* __restrict__ Blo,
                               const float* __restrict__ bias, float* __restrict__ C,
                               int row0, int K, int Ntot, int col0) {
    extern __shared__ __align__(16) __nv_bfloat16 smb[];
    uint32_t sbase = smem_u32(smb);
    int tid = threadIdx.x;
    int wid = tid >> 5, lane = tid & 31;
    int wm = wid >> 2, wn = wid & 3, gr = lane >> 2, tg = lane & 3;

    float acc[4][4][4] = {};
    int nch = K >> 5;

    auto issue = [&](int c) {
        int kt = c << 5;
        uint32_t base = sbase + (uint32_t)(c & 1) * (STAGE_ELEMS * 2);
#pragma unroll
        for (int it = 0; it < 2; it++) {
            int idx = it * 256 + tid;
            int row = idx >> 2, g8 = (idx & 3) * 8;
            size_t goff = (size_t)(row0 + row) * K + kt + g8;
            uint32_t d = base + (uint32_t)(row * GSTR + g8) * 2;
            cp16(d, Ahi + goff);
            cp16(d + GST_ELEMS * 2, Alo + goff);
        }
#pragma unroll
        for (int it = 0; it < 2; it++) {
            int idx = it * 256 + tid;
            int n = idx >> 2, g8 = (idx & 3) * 8;
            size_t goff = (size_t)(col0 + n) * K + kt + g8;
            uint32_t d = base + (uint32_t)(2 * GST_ELEMS + n * GSTR + g8) * 2;
            cp16(d, Bhi + goff);
            cp16(d + GST_ELEMS * 2, Blo + goff);
        }
        cp_commit();
    };

    issue(0);
    for (int c = 0; c < nch; c++) {
        if (c + 1 < nch) { issue(c + 1); cp_wait<1>(); }
        else             { cp_wait<0>(); }
        __syncthreads();

        const uint32_t* S = reinterpret_cast<const uint32_t*>(smb) + (c & 1) * (STAGE_ELEMS / 2);
        const uint32_t* A32h = S;
        const uint32_t* A32l = S + GST_ELEMS / 2;
        const uint32_t* B32h = S + GST_ELEMS;
        const uint32_t* B32l = S + GST_ELEMS + GST_ELEMS / 2;

#pragma unroll
        for (int ks = 0; ks < 2; ks++) {
            int kb = ks * 8;  // k-pair offset (k0 = ks*16)
            uint32_t ah[4][4], al[4][4], bh[4][2], bl[4][2];
#pragma unroll
            for (int mt = 0; mt < 4; mt++) {
                int r = wm * 64 + mt * 16 + gr;
                int o = r * (GSTR / 2) + kb + tg;
                ah[mt][0] = A32h[o];
                ah[mt][1] = A32h[o + 8 * (GSTR / 2)];
                ah[mt][2] = A32h[o + 4];
                ah[mt][3] = A32h[o + 8 * (GSTR / 2) + 4];
                al[mt][0] = A32l[o];
                al[mt][1] = A32l[o + 8 * (GSTR / 2)];
                al[mt][2] = A32l[o + 4];
                al[mt][3] = A32l[o + 8 * (GSTR / 2) + 4];
            }
#pragma unroll
            for (int nt = 0; nt < 4; nt++) {
                int n = wn * 32 + nt * 8 + gr;
                int o = n * (GSTR / 2) + kb + tg;
                bh[nt][0] = B32h[o];
                bh[nt][1] = B32h[o + 4];
                bl[nt][0] = B32l[o];
                bl[nt][1] = B32l[o + 4];
            }
#pragma unroll
            for (int mt = 0; mt < 4; mt++)
#pragma unroll
                for (int nt = 0; nt < 4; nt++) {
                    mma_bf16(acc[mt][nt], ah[mt], bh[nt]);
                    mma_bf16(acc[mt][nt], ah[mt], bl[nt]);
                    mma_bf16(acc[mt][nt], al[mt], bh[nt]);
                }
        }
        __syncthreads();
    }

    // ---- epilogue ----
#pragma unroll
    for (int mt = 0; mt < 4; mt++) {
#pragma unroll
        for (int nt = 0; nt < 4; nt++) {
            int row = row0 + wm * 64 + mt * 16 + gr;
            int col = col0 + wn * 32 + nt * 8 + 2 * tg;
            float b0 = 0.f, b1 = 0.f;
            if (bias) { b0 = bias[col]; b1 = bias[col + 1]; }
            float2 o0 = {acc[mt][nt][0] + b0, acc[mt][nt][1] + b1};
            float2 o1 = {acc[mt][nt][2] + b0, acc[mt][nt][3] + b1};
            *(float2*)&C[(size_t)row * Ntot + col] = o0;
            *(float2*)&C[(size_t)(row + 8) * Ntot + col] = o1;
        }
    }
}

// QKVS fused: blockIdx.y selects weight/bias/output
__global__ __launch_bounds__(256) void bf16_gemm_qkvs(
    const __nv_bfloat16* __restrict__ Ahi, const __nv_bfloat16* __restrict__ Alo,
    const float* __restrict__ bq, float* __restrict__ Cq,
    const float* __restrict__ bk, float* __restrict__ Ck,
    const float* __restrict__ bv, float* __restrict__ Cv,
    const float* __restrict__ bs, float* __restrict__ Cs) {
    const __nv_bfloat16 *Bh, *Bl; const float* bias; float* C;
    switch (blockIdx.y) {
        case 0: Bh = g_wtq_hi; Bl = g_wtq_lo; bias = bq; C = Cq; break;
        case 1: Bh = g_wtk_hi; Bl = g_wtk_lo; bias = bk; C = Ck; break;
        case 2: Bh = g_wtv_hi; Bl = g_wtv_lo; bias = bv; C = Cv; break;
        default: Bh = g_wts_hi; Bl = g_wts_lo; bias = bs; C = Cs; break;
    }
    bf16_gemm_body(Ahi, Alo, Bh, Bl, bias, C, blockIdx.x * 128, E_, E_, 0);
}

__global__ __launch_bounds__(256) void bf16_gemm(
    const __nv_bfloat16* __restrict__ Ahi, const __nv_bfloat16* __restrict__ Alo,
    const __nv_bfloat16* __restrict__ Bhi, const __nv_bfloat16* __restrict__ Blo,
    float* __restrict__ C, int K, int Ntot) {
    bf16_gemm_body(Ahi, Alo, Bhi, Blo, nullptr, C, blockIdx.x * 128, K, Ntot, blockIdx.y * 128);
}

// ---------------- CSR build ----------------
__global__ void zero_deg_kernel() {
    int i = blockIdx.x * blockDim.x + threadIdx.x;
    if (i < NM_) g_deg_m[i] = 0;
    if (i < NO_) g_deg_o[i] = 0;
}

__global__ void count_kernel(const int* __restrict__ dst, int* __restrict__ deg, int ne) {
    int e = blockIdx.x * blockDim.x + threadIdx.x;
    if (e < ne) atomicAdd(&deg[dst[e]], 1);
}

__global__ void scan_local_kernel(const int* __restrict__ deg, int* __restrict__ off,
                                  int* __restrict__ bsum) {
    __shared__ int ws[8];
    int tid = threadIdx.x;
    int base = blockIdx.x * 1024 + tid * 4;
    int4 d = *(const int4*)&deg[base];
    int s = d.x + d.y + d.z + d.w;
    int lane = tid & 31, wid = tid >> 5;
    int v = s;
#pragma unroll
    for (int o = 1; o < 32; o <<= 1) {
        int t = __shfl_up_sync(0xffffffffu, v, o);
        if (lane >= o) v += t;
    }
    if (lane == 31) ws[wid] = v;
    __syncthreads();
    if (tid == 0) {
        int run = 0;
#pragma unroll
        for (int w = 0; w < 8; w++) { int t = ws[w]; ws[w] = run; run += t; }
    }
    __syncthreads();
    int excl = v - s + ws[wid];
    int4 o4;
    o4.x = excl;
    o4.y = excl + d.x;
    o4.z = o4.y + d.y;
    o4.w = o4.z + d.z;
    *(int4*)&off[base] = o4;
    if (tid == 255) bsum[blockIdx.x] = excl + s;
}

__global__ void scan_bsums_kernel(int* __restrict__ bsum, int nb, int* __restrict__ off, int n) {
    __shared__ int sh[128];
    int tid = threadIdx.x;
    int val = (tid < nb) ? bsum[tid] : 0;
    sh[tid] = val;
    __syncthreads();
    int acc = val;
    for (int o = 1; o < 128; o <<= 1) {
        int t = (tid >= o) ? sh[tid - o] : 0;
        __syncthreads();
        acc += t;
        sh[tid] = acc;
        __syncthreads();
    }
    if (tid < nb) bsum[tid] = acc - val;
    if (tid == 127) off[n] = sh[127];
}

__global__ void scan_add_kernel(int* __restrict__ off, int* __restrict__ pos,
                                const int* __restrict__ bsum, int n) {
    int i = blockIdx.x * blockDim.x + threadIdx.x;
    if (i < n) {
        int v = off[i] + bsum[i >> 10];
        off[i] = v;
        pos[i] = v;
    }
}

__global__ void scatter_kernel(const int* __restrict__ src, const int* __restrict__ dst,
                               int* __restrict__ pos, int* __restrict__ csr, int ne) {
    int e = blockIdx.x * blockDim.x + threadIdx.x;
    if (e < ne) {
        int t = dst[e];
        int slot = atomicAdd(&pos[t], 1);
        csr[slot] = src[e];
    }
}

__global__ void dinv_kernel() {
    int i = blockIdx.x * blockDim.x + threadIdx.x;
    if (i < NO_) g_dinv[i] = rsqrtf((float)(g_deg_o[i] + 1));
}

// ---------------- masked mean (fp32 out) ----------------
__global__ void masked_mean4_kernel(const int* __restrict__ tok,
                                    const float* __restrict__ table,
                                    float* __restrict__ out, int L) {
    __shared__ int ts[4][64];
    int warp = threadIdx.x >> 5, lane = threadIdx.x & 31;
    int n = blockIdx.x * 4 + warp;
    for (int j = lane; j < L; j += 32) ts[warp][j] = tok[n * L + j];
    __syncwarp();
    const float4* t4 = (const float4*)table;
    float4 acc = {0.f, 0.f, 0.f, 0.f};
    int cnt = 0;
    for (int j = 0; j < L; j++) {
        int t = ts[warp][j];
        if (t != 0) {
            float4 e = t4[(size_t)t * 32 + lane];
            acc.x += e.x; acc.y += e.y; acc.z += e.z; acc.w += e.w;
            cnt++;
        }
    }
    float inv = 1.f / (float)(cnt > 1 ? cnt : 1);
    float4 o = {acc.x * inv, acc.y * inv, acc.z * inv, acc.w * inv};
    ((float4*)out)[(size_t)n * 32 + lane] = o;
}

// ---------------- masked mean (bf16 hi/lo out, for mini) ----------------
__global__ void masked_mean4_bf16_kernel(const int* __restrict__ tok,
                                         const float* __restrict__ table,
                                         __nv_bfloat16* __restrict__ hi,
                                         __nv_bfloat16* __restrict__ lo, int L) {
    __shared__ int ts[4][64];
    int warp = threadIdx.x >> 5, lane = threadIdx.x & 31;
    int n = blockIdx.x * 4 + warp;
    for (int j = lane; j < L; j += 32) ts[warp][j] = tok[n * L + j];
    __syncwarp();
    const float4* t4 = (const float4*)table;
    float4 acc = {0.f, 0.f, 0.f, 0.f};
    int cnt = 0;
    for (int j = 0; j < L; j++) {
        int t = ts[warp][j];
        if (t != 0) {
            float4 e = t4[(size_t)t * 32 + lane];
            acc.x += e.x; acc.y += e.y; acc.z += e.z; acc.w += e.w;
            cnt++;
        }
    }
    float inv = 1.f / (float)(cnt > 1 ? cnt : 1);
    float4 o = {acc.x * inv, acc.y * inv, acc.z * inv, acc.w * inv};
    split_store4(hi, lo, ((size_t)n * 32 + lane) * 4, o);
}

// ---------------- fused transformer-conv attention (one warp per dst node) -------
__global__ void attn_kernel() {
    int warp = threadIdx.x >> 5, lane = threadIdx.x & 31;
    int t = blockIdx.x * 8 + warp;
    const float4* q4 = (const float4*)g_q;
    const float4* k4 = (const float4*)g_k;
    const float4* v4 = (const float4*)g_v;
    float4 qv = q4[(size_t)t * 32 + lane];
    float m = -1e30f, ss = 0.f;
    float4 acc = {0.f, 0.f, 0.f, 0.f};
    int beg = g_off_m[t], end = g_off_m[t + 1];
    for (int i = beg; i < end; i++) {
        int s = g_csr_m[i];
        float4 kv = k4[(size_t)s * 32 + lane];
        float p = qv.x * kv.x + qv.y * kv.y + qv.z * kv.z + qv.w * kv.w;
        p += __shfl_xor_sync(0xffffffffu, p, 1);
        p += __shfl_xor_sync(0xffffffffu, p, 2);
        float sc = p * 0.25f;
        float mn = fmaxf(m, sc);
        float scale = __expf(m - mn);
        float w = __expf(sc - mn);
        float4 vv = v4[(size_t)s * 32 + lane];
        ss = ss * scale + w;
        acc.x = acc.x * scale + w * vv.x;
        acc.y = acc.y * scale + w * vv.y;
        acc.z = acc.z * scale + w * vv.z;
        acc.w = acc.w * scale + w * vv.w;
        m = mn;
    }
    float inv = 1.f / (ss + 1e-16f);
    float4* h4 = (float4*)g_hidden;
    float4 h = h4[(size_t)t * 32 + lane];
    h.x += acc.x * inv; h.y += acc.y * inv;
    h.z += acc.z * inv; h.w += acc.w * inv;
    h4[(size_t)t * 32 + lane] = h;
}

// ---------------- global attention (segments of 8) -> minifn bf16 hi/lo ----------
__global__ void gattn8_kernel(const float* __restrict__ Wg, const float* __restrict__ bg) {
    int warp = threadIdx.x >> 5;
    int lane = threadIdx.x & 31;
    int n = blockIdx.x * 8 + warp;
    const float4* x4 = (const float4*)g_hidden;
    float4 wg = ((const float4*)Wg)[lane];
    float bgv = bg[0];
    float4 xr[8];
    float g[8];
#pragma unroll
    for (int j = 0; j < 8; j++) {
        float4 xv = x4[(size_t)(n * 8 + j) * 32 + lane];
        xr[j] = xv;
        float p = xv.x * wg.x + xv.y * wg.y + xv.z * wg.z + xv.w * wg.w;
#pragma unroll
        for (int off = 16; off; off >>= 1) p += __shfl_xor_sync(0xffffffffu, p, off);
        g[j] = p + bgv;
    }
    float m = g[0];
#pragma unroll
    for (int j = 1; j < 8; j++) m = fmaxf(m, g[j]);
    float ej[8], s = 0.f;
#pragma unroll
    for (int j = 0; j < 8; j++) { ej[j] = __expf(g[j] - m); s += ej[j]; }
    float inv = 1.f / (s + 1e-16f);
    float4 o = {0.f, 0.f, 0.f, 0.f};
#pragma unroll
    for (int j = 0; j < 8; j++) {
        float a = ej[j] * inv;
        o.x += a * xr[j].x; o.y += a * xr[j].y; o.z += a * xr[j].z; o.w += a * xr[j].w;
    }
    float4 st = ((const float4*)g_stmt)[(size_t)n * 32 + lane];
    float4 res = {(o.x + st.x) * 0.5f, (o.y + st.y) * 0.5f,
                  (o.z + st.z) * 0.5f, (o.w + st.w) * 0.5f};
    split_store4(g_mfn_hi, g_mfn_lo, ((size_t)n * 32 + lane) * 4, res);
}

// ---------------- GCN gather -> relu + bf16 split (for gc1) ----------------------
__global__ void gcn_gather_split_kernel(const float* __restrict__ xw,
                                        const float* __restrict__ bias,
                                        __nv_bfloat16* __restrict__ hi,
                                        __nv_bfloat16* __restrict__ lo, int Mv4) {
    int warp = threadIdx.x >> 5, lane = threadIdx.x & 31;
    int t = blockIdx.x * 8 + warp;
    float di = g_dinv[t];
    int beg = g_off_o[t], end = g_off_o[t + 1];
    const float4* x4 = (const float4*)xw;
    for (int c = lane; c < Mv4; c += 32) {
        float4 a = x4[(size_t)t * Mv4 + c];
        float4 bv = ((const float4*)bias)[c];
        float d2 = di * di;
        float4 acc = {a.x * d2 + bv.x, a.y * d2 + bv.y, a.z * d2 + bv.z, a.w * d2 + bv.w};
        for (int i = beg; i < end; i++) {
            int s = g_csr_o[i];
            float nr = g_dinv[s] * di;
            float4 x = x4[(size_t)s * Mv4 + c];
            acc.x += nr * x.x; acc.y += nr * x.y;
            acc.z += nr * x.z; acc.w += nr * x.w;
        }
        acc.x = fmaxf(acc.x, 0.f); acc.y = fmaxf(acc.y, 0.f);
        acc.z = fmaxf(acc.z, 0.f); acc.w = fmaxf(acc.w, 0.f);
        split_store4(hi, lo, ((size_t)t * Mv4 + c) * 4, acc);
    }
}

// ---------------- GCN gather -> fp32 (for final_stmt) ----------------------------
__global__ void gcn_gather_kernel(const float* __restrict__ xw, const float* __restrict__ bias,
                                  float* __restrict__ out, int Mv4) {
    int warp = threadIdx.x >> 5, lane = threadIdx.x & 31;
    int t = blockIdx.x * 8 + warp;
    float di = g_dinv[t];
    int beg = g_off_o[t], end = g_off_o[t + 1];
    const float4* x4 = (const float4*)xw;
    for (int c = lane; c < Mv4; c += 32) {
        float4 a = x4[(size_t)t * Mv4 + c];
        float4 bv = ((const float4*)bias)[c];
        float d2 = di * di;
        float4 acc = {a.x * d2 + bv.x, a.y * d2 + bv.y, a.z * d2 + bv.z, a.w * d2 + bv.w};
        for (int i = beg; i < end; i++) {
            int s = g_csr_o[i];
            float nr = g_dinv[s] * di;
            float4 x = x4[(size_t)s * Mv4 + c];
            acc.x += nr * x.x; acc.y += nr * x.y;
            acc.z += nr * x.z; acc.w += nr * x.w;
        }
        ((float4*)out)[(size_t)t * Mv4 + c] = acc;
    }
}

// ---------------- global attention (segments of 40) ----------------
__global__ void gattn40_kernel(const float* __restrict__ Wg, const float* __restrict__ bg) {
    __shared__ float gate[40];
    __shared__ float alpha[40];
    __shared__ float ms[2];
    int b = blockIdx.x;
    int tid = threadIdx.x;
    int warp = tid >> 5, lane = tid & 31;
    float4 wg = ((const float4*)Wg)[lane];
    for (int j = warp; j < 40; j += 4) {
        float4 xv = ((const float4*)g_fs)[(size_t)(b * 40 + j) * 32 + lane];
        float p = xv.x * wg.x + xv.y * wg.y + xv.z * wg.z + xv.w * wg.w;
#pragma unroll
        for (int off = 16; off; off >>= 1) p += __shfl_xor_sync(0xffffffffu, p, off);
        if (lane == 0) gate[j] = p + bg[0];
    }
    __syncthreads();
    if (tid == 0) {
        float m = gate[0];
        for (int j = 1; j < 40; j++) m = fmaxf(m, gate[j]);
        float s = 0.f;
        for (int j = 0; j < 40; j++) s += __expf(gate[j] - m);
        ms[0] = m; ms[1] = s;
    }
    __syncthreads();
    if (tid < 40) alpha[tid] = __expf(gate[tid] - ms[0]) / (ms[1] + 1e-16f);
    __syncthreads();
    float acc = 0.f;
    for (int j = 0; j < 40; j++)
        acc += alpha[j] * g_fs[(size_t)(b * 40 + j) * E_ + tid];
    g_fn[(size_t)b * E_ + tid] = acc;
}

// ---------------- cosine ----------------
__global__ void cos_kernel(float* __restrict__ out) {
    int warp = threadIdx.x >> 5, lane = threadIdx.x & 31;
    int b = blockIdx.x * 8 + warp;
    float4 a4 = ((const float4*)g_fn)[(size_t)b * 32 + lane];
    float4 b4 = ((const float4*)g_hn)[(size_t)b * 32 + lane];
    float dt = a4.x * b4.x + a4.y * b4.y + a4.z * b4.z + a4.w * b4.w;
    float na = a4.x * a4.x + a4.y * a4.y + a4.z * a4.z + a4.w * a4.w;
    float nb = b4.x * b4.x + b4.y * b4.y + b4.z * b4.z + b4.w * b4.w;
#pragma unroll
    for (int off = 16; off; off >>= 1) {
        dt += __shfl_xor_sync(0xffffffffu, dt, off);
        na += __shfl_xor_sync(0xffffffffu, na, off);
        nb += __shfl_xor_sync(0xffffffffu, nb, off);
    }
    if (lane == 0)
        out[b] = dt / (fmaxf(sqrtf(na), 1e-8f) * fmaxf(sqrtf(nb), 1e-8f));
}

// ---------------- launch ----------------
extern "C" void kernel_launch(void* const* d_in, const int* in_sizes, int n_in,
                              void* d_out, int out_size) {
    const int* desc_tokens = (const int*)d_in[0];
    const int* x_tokens    = (const int*)d_in[1];
    const int* mini_tokens = (const int*)d_in[2];
    const int* src         = (const int*)d_in[3];
    const int* dst         = (const int*)d_in[4];
    const int* mini_src    = (const int*)d_in[5];
    const int* mini_dst    = (const int*)d_in[6];
    const float* desc_table  = (const float*)d_in[9];
    const float* code_table  = (const float*)d_in[10];
    const float* code_table2 = (const float*)d_in[11];
    const float* Wq = (const float*)d_in[12]; const float* bq = (const float*)d_in[13];
    const float* Wk = (const float*)d_in[14]; const float* bk = (const float*)d_in[15];
    const float* Wv = (const float*)d_in[16]; const float* bv = (const float*)d_in[17];
    const float* Wskip = (const float*)d_in[18]; const float* bskip = (const float*)d_in[19];
    const float* W2 = (const float*)d_in[20]; const float* b2 = (const float*)d_in[21];
    const float* W3 = (const float*)d_in[22]; const float* b3 = (const float*)d_in[23];
    const float* Wg = (const float*)d_in[24]; const float* bg = (const float*)d_in[25];
    float* out = (float*)d_out;

    float *p_q, *p_k, *p_v, *p_hidden, *p_hn, *p_stmt;
    float *p_xw1, *p_xw2, *p_fs;
    cudaGetSymbolAddress((void**)&p_q, g_q);
    cudaGetSymbolAddress((void**)&p_k, g_k);
    cudaGetSymbolAddress((void**)&p_v, g_v);
    cudaGetSymbolAddress((void**)&p_hidden, g_hidden);
    cudaGetSymbolAddress((void**)&p_hn, g_hn);
    cudaGetSymbolAddress((void**)&p_stmt, g_stmt);
    cudaGetSymbolAddress((void**)&p_xw1, g_xw1);
    cudaGetSymbolAddress((void**)&p_xw2, g_xw2);
    cudaGetSymbolAddress((void**)&p_fs, g_fs);

    __nv_bfloat16 *p_mini_hi, *p_mini_lo, *p_mfn_hi, *p_mfn_lo, *p_gc1_hi, *p_gc1_lo;
    __nv_bfloat16 *p_wtq_hi, *p_wtq_lo, *p_wtk_hi, *p_wtk_lo, *p_wtv_hi, *p_wtv_lo;
    __nv_bfloat16 *p_wts_hi, *p_wts_lo, *p_w2t_hi, *p_w2t_lo, *p_w3t_hi, *p_w3t_lo;
    cudaGetSymbolAddress((void**)&p_mini_hi, g_mini_hi);
    cudaGetSymbolAddress((void**)&p_mini_lo, g_mini_lo);
    cudaGetSymbolAddress((void**)&p_mfn_hi, g_mfn_hi);
    cudaGetSymbolAddress((void**)&p_mfn_lo, g_mfn_lo);
    cudaGetSymbolAddress((void**)&p_gc1_hi, g_gc1_hi);
    cudaGetSymbolAddress((void**)&p_gc1_lo, g_gc1_lo);
    cudaGetSymbolAddress((void**)&p_wtq_hi, g_wtq_hi);
    cudaGetSymbolAddress((void**)&p_wtq_lo, g_wtq_lo);
    cudaGetSymbolAddress((void**)&p_wtk_hi, g_wtk_hi);
    cudaGetSymbolAddress((void**)&p_wtk_lo, g_wtk_lo);
    cudaGetSymbolAddress((void**)&p_wtv_hi, g_wtv_hi);
    cudaGetSymbolAddress((void**)&p_wtv_lo, g_wtv_lo);
    cudaGetSymbolAddress((void**)&p_wts_hi, g_wts_hi);
    cudaGetSymbolAddress((void**)&p_wts_lo, g_wts_lo);
    cudaGetSymbolAddress((void**)&p_w2t_hi, g_w2t_hi);
    cudaGetSymbolAddress((void**)&p_w2t_lo, g_w2t_lo);
    cudaGetSymbolAddress((void**)&p_w3t_hi, g_w3t_hi);
    cudaGetSymbolAddress((void**)&p_w3t_lo, g_w3t_lo);

    int *p_deg_m, *p_off_m, *p_pos_m, *p_csr_m, *p_bsum_m;
    int *p_deg_o, *p_off_o, *p_pos_o, *p_csr_o, *p_bsum_o;
    cudaGetSymbolAddress((void**)&p_deg_m, g_deg_m);
    cudaGetSymbolAddress((void**)&p_off_m, g_off_m);
    cudaGetSymbolAddress((void**)&p_pos_m, g_pos_m);
    cudaGetSymbolAddress((void**)&p_csr_m, g_csr_m);
    cudaGetSymbolAddress((void**)&p_bsum_m, g_bsum_m);
    cudaGetSymbolAddress((void**)&p_deg_o, g_deg_o);
    cudaGetSymbolAddress((void**)&p_off_o, g_off_o);
    cudaGetSymbolAddress((void**)&p_pos_o, g_pos_o);
    cudaGetSymbolAddress((void**)&p_csr_o, g_csr_o);
    cudaGetSymbolAddress((void**)&p_bsum_o, g_bsum_o);

    cudaFuncSetAttribute(bf16_gemm_qkvs, cudaFuncAttributeMaxDynamicSharedMemorySize, GEMM_SMEM);
    cudaFuncSetAttribute(bf16_gemm, cudaFuncAttributeMaxDynamicSharedMemorySize, GEMM_SMEM);

    // ---- weight transpose + split (small, independent) ----
    wsplit_kernel<<<(E_ * E_ + 255) / 256, 256>>>(Wq, p_wtq_hi, p_wtq_lo, E_, E_);
    wsplit_kernel<<<(E_ * E_ + 255) / 256, 256>>>(Wk, p_wtk_hi, p_wtk_lo, E_, E_);
    wsplit_kernel<<<(E_ * E_ + 255) / 256, 256>>>(Wv, p_wtv_hi, p_wtv_lo, E_, E_);
    wsplit_kernel<<<(E_ * E_ + 255) / 256, 256>>>(Wskip, p_wts_hi, p_wts_lo, E_, E_);
    wsplit_kernel<<<(E_ * HID_ + 255) / 256, 256>>>(W2, p_w2t_hi, p_w2t_lo, E_, HID_);
    wsplit_kernel<<<(HID_ * E_ + 255) / 256, 256>>>(W3, p_w3t_hi, p_w3t_lo, HID_, E_);

    // ---- CSR build ----
    zero_deg_kernel<<<(NM_ + 255) / 256, 256>>>();
    count_kernel<<<(EM_ + 255) / 256, 256>>>(mini_dst, p_deg_m, EM_);
    count_kernel<<<(EO_ + 255) / 256, 256>>>(dst, p_deg_o, EO_);
    scan_local_kernel<<<NM_ / 1024, 256>>>(p_deg_m, p_off_m, p_bsum_m);
    scan_local_kernel<<<NO_ / 1024, 256>>>(p_deg_o, p_off_o, p_bsum_o);
    scan_bsums_kernel<<<1, 128>>>(p_bsum_m, NM_ / 1024, p_off_m, NM_);
    scan_bsums_kernel<<<1, 128>>>(p_bsum_o, NO_ / 1024, p_off_o, NO_);
    scan_add_kernel<<<NM_ / 256, 256>>>(p_off_m, p_pos_m, p_bsum_m, NM_);
    scan_add_kernel<<<NO_ / 256, 256>>>(p_off_o, p_pos_o, p_bsum_o, NO_);
    dinv_kernel<<<(NO_ + 255) / 256, 256>>>();
    scatter_kernel<<<(EM_ + 255) / 256, 256>>>(mini_src, mini_dst, p_pos_m, p_csr_m, EM_);
    scatter_kernel<<<(EO_ + 255) / 256, 256>>>(src, dst, p_pos_o, p_csr_o, EO_);

    // ---- embeddings ----
    masked_mean4_kernel<<<B_ / 4, 128>>>(desc_tokens, desc_table, p_hn, LD_);
    masked_mean4_kernel<<<NO_ / 4, 128>>>(x_tokens, code_table2, p_stmt, LO_);
    masked_mean4_bf16_kernel<<<NM_ / 4, 128>>>(mini_tokens, code_table, p_mini_hi, p_mini_lo, LM_);

    // ---- fused q,k,v,skip projections (bf16x3 mma.sync) ----
    {
        dim3 grid(NM_ / 128, 4);
        bf16_gemm_qkvs<<<grid, 256, GEMM_SMEM>>>(p_mini_hi, p_mini_lo,
                                                 bq, p_q, bk, p_k, bv, p_v, bskip, p_hidden);
    }

    // ---- fused attention ----
    attn_kernel<<<NM_ / 8, 256>>>();

    // ---- global attention (segments of 8) -> minifn bf16 ----
    gattn8_kernel<<<NO_ / 8, 256>>>(Wg, bg);

    // ---- GCN layer 1: xw1 = minifn @ W2 ----
    {
        dim3 grid(NO_ / 128, HID_ / 128);
        bf16_gemm<<<grid, 256, GEMM_SMEM>>>(p_mfn_hi, p_mfn_lo, p_w2t_hi, p_w2t_lo,
                                            p_xw1, E_, HID_);
    }
    gcn_gather_split_kernel<<<NO_ / 8, 256>>>(p_xw1, b2, p_gc1_hi, p_gc1_lo, HID_ / 4);

    // ---- GCN layer 2: xw2 = relu(gc1) @ W3 (relu already folded into gc1) ----
    {
        dim3 grid(NO_ / 128, E_ / 128);
        bf16_gemm<<<grid, 256, GEMM_SMEM>>>(p_gc1_hi, p_gc1_lo, p_w3t_hi, p_w3t_lo,
                                            p_xw2, HID_, E_);
    }
    gcn_gather_kernel<<<NO_ / 8, 256>>>(p_xw2, b3, p_fs, E_ / 4);

    // ---- readout ----
    gattn40_kernel<<<B_, E_>>>(Wg, bg);
    cos_kernel<<<B_ / 8, 256>>>(out);
    (void)in_sizes; (void)n_in; (void)out_size;
}

// round 8
// speedup vs baseline: 3.4165x; 1.1477x over previous
#include <cuda_runtime.h>
#include <cuda_bf16.h>
#include <cstdint>

#define B_   256
#define LD_  64
#define NO_  10240
#define LO_  32
#define NM_  81920
#define LM_  16
#define EO_  81920
#define EM_  327680
#define E_   128
#define HID_ 256
#define H_   8
#define Dh_  16

// ---------------- scratch ----------------
__device__ float g_hn[B_ * E_];
__device__ float g_stmt[NO_ * E_];
__device__ float g_q[NM_ * E_];
__device__ float g_k[NM_ * E_];
__device__ float g_v[NM_ * E_];
__device__ float g_hidden[NM_ * E_];
__device__ float g_dinv[NO_];
__device__ float g_xw1[NO_ * HID_];
__device__ float g_xw2[NO_ * E_];
__device__ float g_fs[NO_ * E_];
__device__ float g_fn[B_ * E_];

// bf16 split operand buffers
__device__ __align__(16) __nv_bfloat16 g_mini_hi[NM_ * E_], g_mini_lo[NM_ * E_];
__device__ __align__(16) __nv_bfloat16 g_mfn_hi[NO_ * E_],  g_mfn_lo[NO_ * E_];
__device__ __align__(16) __nv_bfloat16 g_gc1_hi[NO_ * HID_], g_gc1_lo[NO_ * HID_];
__device__ __align__(16) __nv_bfloat16 g_wtq_hi[E_ * E_], g_wtq_lo[E_ * E_];
__device__ __align__(16) __nv_bfloat16 g_wtk_hi[E_ * E_], g_wtk_lo[E_ * E_];
__device__ __align__(16) __nv_bfloat16 g_wtv_hi[E_ * E_], g_wtv_lo[E_ * E_];
__device__ __align__(16) __nv_bfloat16 g_wts_hi[E_ * E_], g_wts_lo[E_ * E_];
__device__ __align__(16) __nv_bfloat16 g_w2t_hi[HID_ * E_], g_w2t_lo[HID_ * E_];
__device__ __align__(16) __nv_bfloat16 g_w3t_hi[E_ * HID_], g_w3t_lo[E_ * HID_];

__device__ int g_deg_m[NM_];
__device__ int g_off_m[NM_ + 1];
__device__ int g_pos_m[NM_];
__device__ int g_csr_m[EM_];
__device__ int g_bsum_m[256];
__device__ int g_deg_o[NO_];
__device__ int g_off_o[NO_ + 1];
__device__ int g_pos_o[NO_];
__device__ int g_csr_o[EO_];
__device__ int g_bsum_o[256];

// ---------------- helpers ----------------
__device__ __forceinline__ uint32_t smem_u32(const void* p) {
    uint32_t a;
    asm("{ .reg .u64 t; cvta.to.shared.u64 t, %1; cvt.u32.u64 %0, t; }" : "=r"(a) : "l"(p));
    return a;
}
__device__ __forceinline__ void cp16(uint32_t dst, const void* src) {
    asm volatile("cp.async.cg.shared.global [%0], [%1], 16;" :: "r"(dst), "l"(src));
}
__device__ __forceinline__ void cp_commit() {
    asm volatile("cp.async.commit_group;" ::: "memory");
}
template <int N>
__device__ __forceinline__ void cp_wait() {
    asm volatile("cp.async.wait_group %0;" :: "n"(N) : "memory");
}
__device__ __forceinline__ void mma_bf16(float* d, const uint32_t* a, const uint32_t* b) {
    asm volatile(
        "mma.sync.aligned.m16n8k16.row.col.f32.bf16.bf16.f32 "
        "{%0,%1,%2,%3}, {%4,%5,%6,%7}, {%8,%9}, {%0,%1,%2,%3};"
        : "+f"(d[0]), "+f"(d[1]), "+f"(d[2]), "+f"(d[3])
        : "r"(a[0]), "r"(a[1]), "r"(a[2]), "r"(a[3]), "r"(b[0]), "r"(b[1]));
}

__device__ __forceinline__ void split_store4(__nv_bfloat16* hi, __nv_bfloat16* lo,
                                             size_t base, float4 v) {
    __nv_bfloat162 h0 = __floats2bfloat162_rn(v.x, v.y);
    __nv_bfloat162 h1 = __floats2bfloat162_rn(v.z, v.w);
    float rx = __bfloat162float(h0.x), ry = __bfloat162float(h0.y);
    float rz = __bfloat162float(h1.x), rw = __bfloat162float(h1.y);
    __nv_bfloat162 l0 = __floats2bfloat162_rn(v.x - rx, v.y - ry);
    __nv_bfloat162 l1 = __floats2bfloat162_rn(v.z - rz, v.w - rw);
    uint2 hp = {*(uint32_t*)&h0, *(uint32_t*)&h1};
    uint2 lp = {*(uint32_t*)&l0, *(uint32_t*)&l1};
    *(uint2*)(hi + base) = hp;
    *(uint2*)(lo + base) = lp;
}

// ---------------- weight transpose + split ----------------
__global__ void wsplit_kernel(const float* __restrict__ W, __nv_bfloat16* __restrict__ hi,
                              __nv_bfloat16* __restrict__ lo, int K, int N) {
    int i = blockIdx.x * blockDim.x + threadIdx.x;
    if (i >= K * N) return;
    int n = i / K, k = i - n * K;
    float v = W[(size_t)k * N + n];
    __nv_bfloat16 h = __float2bfloat16(v);
    hi[i] = h;
    lo[i] = __float2bfloat16(v - __bfloat162float(h));
}

// 4 square E_xE_ weights in one launch (blockIdx.y selects)
__global__ void wsplit4_kernel(const float* __restrict__ Wq, const float* __restrict__ Wk,
                               const float* __restrict__ Wv, const float* __restrict__ Ws) {
    const float* W; __nv_bfloat16 *hi, *lo;
    switch (blockIdx.y) {
        case 0: W = Wq; hi = g_wtq_hi; lo = g_wtq_lo; break;
        case 1: W = Wk; hi = g_wtk_hi; lo = g_wtk_lo; break;
        case 2: W = Wv; hi = g_wtv_hi; lo = g_wtv_lo; break;
        default: W = Ws; hi = g_wts_hi; lo = g_wts_lo; break;
    }
    int i = blockIdx.x * blockDim.x + threadIdx.x;
    if (i >= E_ * E_) return;
    int n = i / E_, k = i - n * E_;
    float v = W[(size_t)k * E_ + n];
    __nv_bfloat16 h = __float2bfloat16(v);
    hi[i] = h;
    lo[i] = __float2bfloat16(v - __bfloat162float(h));
}

// ---------------- bf16x3 mma.sync GEMM, cp.async double-buffered -----------------
#define GSTR 40
#define GST_ELEMS (128 * GSTR)
#define STAGE_ELEMS (4 * GST_ELEMS)
#define GEMM_SMEM (2 * STAGE_ELEMS * 2)

__device__ void bf16_gemm_body(const __nv_bfloat16* __restrict__ Ahi,
                               const __nv_bfloat16* __restrict__ Alo,
                               const __nv_bfloat16* __restrict__ Bhi,
                               const __nv_bfloat16* __restrict__ Blo,
                               const float* __restrict__ bias, float* __restrict__ C,
                               int row0, int K, int Ntot, int col0) {
    extern __shared__ __align__(16) __nv_bfloat16 smb[];
    uint32_t sbase = smem_u32(smb);
    int tid = threadIdx.x;
    int wid = tid >> 5, lane = tid & 31;
    int wm = wid >> 2, wn = wid & 3, gr = lane >> 2, tg = lane & 3;

    float acc[4][4][4] = {};
    int nch = K >> 5;

    auto issue = [&](int c) {
        int kt = c << 5;
        uint32_t base = sbase + (uint32_t)(c & 1) * (STAGE_ELEMS * 2);
#pragma unroll
        for (int it = 0; it < 2; it++) {
            int idx = it * 256 + tid;
            int row = idx >> 2, g8 = (idx & 3) * 8;
            size_t goff = (size_t)(row0 + row) * K + kt + g8;
            uint32_t d = base + (uint32_t)(row * GSTR + g8) * 2;
            cp16(d, Ahi + goff);
            cp16(d + GST_ELEMS * 2, Alo + goff);
        }
#pragma unroll
        for (int it = 0; it < 2; it++) {
            int idx = it * 256 + tid;
            int n = idx >> 2, g8 = (idx & 3) * 8;
            size_t goff = (size_t)(col0 + n) * K + kt + g8;
            uint32_t d = base + (uint32_t)(2 * GST_ELEMS + n * GSTR + g8) * 2;
            cp16(d, Bhi + goff);
            cp16(d + GST_ELEMS * 2, Blo + goff);
        }
        cp_commit();
    };

    issue(0);
    for (int c = 0; c < nch; c++) {
        if (c + 1 < nch) { issue(c + 1); cp_wait<1>(); }
        else             { cp_wait<0>(); }
        __syncthreads();

        const uint32_t* S = reinterpret_cast<const uint32_t*>(smb) + (c & 1) * (STAGE_ELEMS / 2);
        const uint32_t* A32h = S;
        const uint32_t* A32l = S + GST_ELEMS / 2;
        const uint32_t* B32h = S + GST_ELEMS;
        const uint32_t* B32l = S + GST_ELEMS + GST_ELEMS / 2;

#pragma unroll
        for (int ks = 0; ks < 2; ks++) {
            int kb = ks * 8;
            uint32_t ah[4][4], al[4][4], bh[4][2], bl[4][2];
#pragma unroll
            for (int mt = 0; mt < 4; mt++) {
                int r = wm * 64 + mt * 16 + gr;
                int o = r * (GSTR / 2) + kb + tg;
                ah[mt][0] = A32h[o];
                ah[mt][1] = A32h[o + 8 * (GSTR / 2)];
                ah[mt][2] = A32h[o + 4];
                ah[mt][3] = A32h[o + 8 * (GSTR / 2) + 4];
                al[mt][0] = A32l[o];
                al[mt][1] = A32l[o + 8 * (GSTR / 2)];
                al[mt][2] = A32l[o + 4];
                al[mt][3] = A32l[o + 8 * (GSTR / 2) + 4];
            }
#pragma unroll
            for (int nt = 0; nt < 4; nt++) {
                int n = wn * 32 + nt * 8 + gr;
                int o = n * (GSTR / 2) + kb + tg;
                bh[nt][0] = B32h[o];
                bh[nt][1] = B32h[o + 4];
                bl[nt][0] = B32l[o];
                bl[nt][1] = B32l[o + 4];
            }
#pragma unroll
            for (int mt = 0; mt < 4; mt++)
#pragma unroll
                for (int nt = 0; nt < 4; nt++) {
                    mma_bf16(acc[mt][nt], ah[mt], bh[nt]);
                    mma_bf16(acc[mt][nt], ah[mt], bl[nt]);
                    mma_bf16(acc[mt][nt], al[mt], bh[nt]);
                }
        }
        __syncthreads();
    }

#pragma unroll
    for (int mt = 0; mt < 4; mt++) {
#pragma unroll
        for (int nt = 0; nt < 4; nt++) {
            int row = row0 + wm * 64 + mt * 16 + gr;
            int col = col0 + wn * 32 + nt * 8 + 2 * tg;
            float b0 = 0.f, b1 = 0.f;
            if (bias) { b0 = bias[col]; b1 = bias[col + 1]; }
            float2 o0 = {acc[mt][nt][0] + b0, acc[mt][nt][1] + b1};
            float2 o1 = {acc[mt][nt][2] + b0, acc[mt][nt][3] + b1};
            *(float2*)&C[(size_t)row * Ntot + col] = o0;
            *(float2*)&C[(size_t)(row + 8) * Ntot + col] = o1;
        }
    }
}

__global__ __launch_bounds__(256) void bf16_gemm_qkvs(
    const __nv_bfloat16* __restrict__ Ahi, const __nv_bfloat16* __restrict__ Alo,
    const float* __restrict__ bq, float* __restrict__ Cq,
    const float* __restrict__ bk, float* __restrict__ Ck,
    const float* __restrict__ bv, float* __restrict__ Cv,
    const float* __restrict__ bs, float* __restrict__ Cs) {
    const __nv_bfloat16 *Bh, *Bl; const float* bias; float* C;
    switch (blockIdx.y) {
        case 0: Bh = g_wtq_hi; Bl = g_wtq_lo; bias = bq; C = Cq; break;
        case 1: Bh = g_wtk_hi; Bl = g_wtk_lo; bias = bk; C = Ck; break;
        case 2: Bh = g_wtv_hi; Bl = g_wtv_lo; bias = bv; C = Cv; break;
        default: Bh = g_wts_hi; Bl = g_wts_lo; bias = bs; C = Cs; break;
    }
    bf16_gemm_body(Ahi, Alo, Bh, Bl, bias, C, blockIdx.x * 128, E_, E_, 0);
}

__global__ __launch_bounds__(256) void bf16_gemm(
    const __nv_bfloat16* __restrict__ Ahi, const __nv_bfloat16* __restrict__ Alo,
    const __nv_bfloat16* __restrict__ Bhi, const __nv_bfloat16* __restrict__ Blo,
    float* __restrict__ C, int K, int Ntot) {
    bf16_gemm_body(Ahi, Alo, Bhi, Blo, nullptr, C, blockIdx.x * 128, K, Ntot, blockIdx.y * 128);
}

// ---------------- CSR build ----------------
__global__ void zero_deg_kernel() {
    int i = blockIdx.x * blockDim.x + threadIdx.x;
    if (i < NM_) g_deg_m[i] = 0;
    if (i < NO_) g_deg_o[i] = 0;
}
__global__ void count_kernel(const int* __restrict__ dst, int* __restrict__ deg, int ne) {
    int e = blockIdx.x * blockDim.x + threadIdx.x;
    if (e < ne) atomicAdd(&deg[dst[e]], 1);
}
__global__ void scan_local_kernel(const int* __restrict__ deg, int* __restrict__ off,
                                  int* __restrict__ bsum) {
    __shared__ int ws[8];
    int tid = threadIdx.x;
    int base = blockIdx.x * 1024 + tid * 4;
    int4 d = *(const int4*)&deg[base];
    int s = d.x + d.y + d.z + d.w;
    int lane = tid & 31, wid = tid >> 5;
    int v = s;
#pragma unroll
    for (int o = 1; o < 32; o <<= 1) {
        int t = __shfl_up_sync(0xffffffffu, v, o);
        if (lane >= o) v += t;
    }
    if (lane == 31) ws[wid] = v;
    __syncthreads();
    if (tid == 0) {
        int run = 0;
#pragma unroll
        for (int w = 0; w < 8; w++) { int t = ws[w]; ws[w] = run; run += t; }
    }
    __syncthreads();
    int excl = v - s + ws[wid];
    int4 o4;
    o4.x = excl;
    o4.y = excl + d.x;
    o4.z = o4.y + d.y;
    o4.w = o4.z + d.z;
    *(int4*)&off[base] = o4;
    if (tid == 255) bsum[blockIdx.x] = excl + s;
}
__global__ void scan_bsums_kernel(int* __restrict__ bsum, int nb, int* __restrict__ off, int n) {
    __shared__ int sh[128];
    int tid = threadIdx.x;
    int val = (tid < nb) ? bsum[tid] : 0;
    sh[tid] = val;
    __syncthreads();
    int acc = val;
    for (int o = 1; o < 128; o <<= 1) {
        int t = (tid >= o) ? sh[tid - o] : 0;
        __syncthreads();
        acc += t;
        sh[tid] = acc;
        __syncthreads();
    }
    if (tid < nb) bsum[tid] = acc - val;
    if (tid == 127) off[n] = sh[127];
}
__global__ void scan_add_kernel(int* __restrict__ off, int* __restrict__ pos,
                                const int* __restrict__ bsum, int n) {
    int i = blockIdx.x * blockDim.x + threadIdx.x;
    if (i < n) {
        int v = off[i] + bsum[i >> 10];
        off[i] = v;
        pos[i] = v;
    }
}
__global__ void scatter_kernel(const int* __restrict__ src, const int* __restrict__ dst,
                               int* __restrict__ pos, int* __restrict__ csr, int ne) {
    int e = blockIdx.x * blockDim.x + threadIdx.x;
    if (e < ne) {
        int t = dst[e];
        int slot = atomicAdd(&pos[t], 1);
        csr[slot] = src[e];
    }
}
__global__ void dinv_kernel() {
    int i = blockIdx.x * blockDim.x + threadIdx.x;
    if (i < NO_) g_dinv[i] = rsqrtf((float)(g_deg_o[i] + 1));
}

// ---------------- masked mean (fp32 out) ----------------
__global__ void masked_mean4_kernel(const int* __restrict__ tok,
                                    const float* __restrict__ table,
                                    float* __restrict__ out, int L) {
    __shared__ int ts[4][64];
    int warp = threadIdx.x >> 5, lane = threadIdx.x & 31;
    int n = blockIdx.x * 4 + warp;
    for (int j = lane; j < L; j += 32) ts[warp][j] = tok[n * L + j];
    __syncwarp();
    const float4* t4 = (const float4*)table;
    float4 acc = {0.f, 0.f, 0.f, 0.f};
    int cnt = 0;
    for (int j = 0; j < L; j++) {
        int t = ts[warp][j];
        if (t != 0) {
            float4 e = t4[(size_t)t * 32 + lane];
            acc.x += e.x; acc.y += e.y; acc.z += e.z; acc.w += e.w;
            cnt++;
        }
    }
    float inv = 1.f / (float)(cnt > 1 ? cnt : 1);
    float4 o = {acc.x * inv, acc.y * inv, acc.z * inv, acc.w * inv};
    ((float4*)out)[(size_t)n * 32 + lane] = o;
}

// ---------------- masked mean (bf16 hi/lo out) ----------------
__global__ void masked_mean4_bf16_kernel(const int* __restrict__ tok,
                                         const float* __restrict__ table,
                                         __nv_bfloat16* __restrict__ hi,
                                         __nv_bfloat16* __restrict__ lo, int L) {
    __shared__ int ts[4][64];
    int warp = threadIdx.x >> 5, lane = threadIdx.x & 31;
    int n = blockIdx.x * 4 + warp;
    for (int j = lane; j < L; j += 32) ts[warp][j] = tok[n * L + j];
    __syncwarp();
    const float4* t4 = (const float4*)table;
    float4 acc = {0.f, 0.f, 0.f, 0.f};
    int cnt = 0;
    for (int j = 0; j < L; j++) {
        int t = ts[warp][j];
        if (t != 0) {
            float4 e = t4[(size_t)t * 32 + lane];
            acc.x += e.x; acc.y += e.y; acc.z += e.z; acc.w += e.w;
            cnt++;
        }
    }
    float inv = 1.f / (float)(cnt > 1 ? cnt : 1);
    float4 o = {acc.x * inv, acc.y * inv, acc.z * inv, acc.w * inv};
    split_store4(hi, lo, ((size_t)n * 32 + lane) * 4, o);
}

// ---------------- fused transformer-conv attention ----------------
__global__ void attn_kernel() {
    int warp = threadIdx.x >> 5, lane = threadIdx.x & 31;
    int t = blockIdx.x * 8 + warp;
    const float4* q4 = (const float4*)g_q;
    const float4* k4 = (const float4*)g_k;
    const float4* v4 = (const float4*)g_v;
    float4 qv = q4[(size_t)t * 32 + lane];
    float m = -1e30f, ss = 0.f;
    float4 acc = {0.f, 0.f, 0.f, 0.f};
    int beg = g_off_m[t], end = g_off_m[t + 1];
    for (int i = beg; i < end; i++) {
        int s = g_csr_m[i];
        float4 kv = k4[(size_t)s * 32 + lane];
        float p = qv.x * kv.x + qv.y * kv.y + qv.z * kv.z + qv.w * kv.w;
        p += __shfl_xor_sync(0xffffffffu, p, 1);
        p += __shfl_xor_sync(0xffffffffu, p, 2);
        float sc = p * 0.25f;
        float mn = fmaxf(m, sc);
        float scale = __expf(m - mn);
        float w = __expf(sc - mn);
        float4 vv = v4[(size_t)s * 32 + lane];
        ss = ss * scale + w;
        acc.x = acc.x * scale + w * vv.x;
        acc.y = acc.y * scale + w * vv.y;
        acc.z = acc.z * scale + w * vv.z;
        acc.w = acc.w * scale + w * vv.w;
        m = mn;
    }
    float inv = 1.f / (ss + 1e-16f);
    float4* h4 = (float4*)g_hidden;
    float4 h = h4[(size_t)t * 32 + lane];
    h.x += acc.x * inv; h.y += acc.y * inv;
    h.z += acc.z * inv; h.w += acc.w * inv;
    h4[(size_t)t * 32 + lane] = h;
}

// ---------------- global attention (segments of 8) -> minifn bf16 ----------------
__global__ void gattn8_kernel(const float* __restrict__ Wg, const float* __restrict__ bg) {
    int warp = threadIdx.x >> 5;
    int lane = threadIdx.x & 31;
    int n = blockIdx.x * 8 + warp;
    const float4* x4 = (const float4*)g_hidden;
    float4 wg = ((const float4*)Wg)[lane];
    float bgv = bg[0];
    float4 xr[8];
    float g[8];
#pragma unroll
    for (int j = 0; j < 8; j++) {
        float4 xv = x4[(size_t)(n * 8 + j) * 32 + lane];
        xr[j] = xv;
        float p = xv.x * wg.x + xv.y * wg.y + xv.z * wg.z + xv.w * wg.w;
#pragma unroll
        for (int off = 16; off; off >>= 1) p += __shfl_xor_sync(0xffffffffu, p, off);
        g[j] = p + bgv;
    }
    float m = g[0];
#pragma unroll
    for (int j = 1; j < 8; j++) m = fmaxf(m, g[j]);
    float ej[8], s = 0.f;
#pragma unroll
    for (int j = 0; j < 8; j++) { ej[j] = __expf(g[j] - m); s += ej[j]; }
    float inv = 1.f / (s + 1e-16f);
    float4 o = {0.f, 0.f, 0.f, 0.f};
#pragma unroll
    for (int j = 0; j < 8; j++) {
        float a = ej[j] * inv;
        o.x += a * xr[j].x; o.y += a * xr[j].y; o.z += a * xr[j].z; o.w += a * xr[j].w;
    }
    float4 st = ((const float4*)g_stmt)[(size_t)n * 32 + lane];
    float4 res = {(o.x + st.x) * 0.5f, (o.y + st.y) * 0.5f,
                  (o.z + st.z) * 0.5f, (o.w + st.w) * 0.5f};
    split_store4(g_mfn_hi, g_mfn_lo, ((size_t)n * 32 + lane) * 4, res);
}

// ---------------- GCN gather -> relu + bf16 split ----------------
__global__ void gcn_gather_split_kernel(const float* __restrict__ xw,
                                        const float* __restrict__ bias,
                                        __nv_bfloat16* __restrict__ hi,
                                        __nv_bfloat16* __restrict__ lo, int Mv4) {
    int warp = threadIdx.x >> 5, lane = threadIdx.x & 31;
    int t = blockIdx.x * 8 + warp;
    float di = g_dinv[t];
    int beg = g_off_o[t], end = g_off_o[t + 1];
    const float4* x4 = (const float4*)xw;
    for (int c = lane; c < Mv4; c += 32) {
        float4 a = x4[(size_t)t * Mv4 + c];
        float4 bv = ((const float4*)bias)[c];
        float d2 = di * di;
        float4 acc = {a.x * d2 + bv.x, a.y * d2 + bv.y, a.z * d2 + bv.z, a.w * d2 + bv.w};
        for (int i = beg; i < end; i++) {
            int s = g_csr_o[i];
            float nr = g_dinv[s] * di;
            float4 x = x4[(size_t)s * Mv4 + c];
            acc.x += nr * x.x; acc.y += nr * x.y;
            acc.z += nr * x.z; acc.w += nr * x.w;
        }
        acc.x = fmaxf(acc.x, 0.f); acc.y = fmaxf(acc.y, 0.f);
        acc.z = fmaxf(acc.z, 0.f); acc.w = fmaxf(acc.w, 0.f);
        split_store4(hi, lo, ((size_t)t * Mv4 + c) * 4, acc);
    }
}

// ---------------- GCN gather -> fp32 ----------------
__global__ void gcn_gather_kernel(const float* __restrict__ xw, const float* __restrict__ bias,
                                  float* __restrict__ out, int Mv4) {
    int warp = threadIdx.x >> 5, lane = threadIdx.x & 31;
    int t = blockIdx.x * 8 + warp;
    float di = g_dinv[t];
    int beg = g_off_o[t], end = g_off_o[t + 1];
    const float4* x4 = (const float4*)xw;
    for (int c = lane; c < Mv4; c += 32) {
        float4 a = x4[(size_t)t * Mv4 + c];
        float4 bv = ((const float4*)bias)[c];
        float d2 = di * di;
        float4 acc = {a.x * d2 + bv.x, a.y * d2 + bv.y, a.z * d2 + bv.z, a.w * d2 + bv.w};
        for (int i = beg; i < end; i++) {
            int s = g_csr_o[i];
            float nr = g_dinv[s] * di;
            float4 x = x4[(size_t)s * Mv4 + c];
            acc.x += nr * x.x; acc.y += nr * x.y;
            acc.z += nr * x.z; acc.w += nr * x.w;
        }
        ((float4*)out)[(size_t)t * Mv4 + c] = acc;
    }
}

// ---------------- global attention (segments of 40) ----------------
__global__ void gattn40_kernel(const float* __restrict__ Wg, const float* __restrict__ bg) {
    __shared__ float gate[40];
    __shared__ float alpha[40];
    __shared__ float ms[2];
    int b = blockIdx.x;
    int tid = threadIdx.x;
    int warp = tid >> 5, lane = tid & 31;
    float4 wg = ((const float4*)Wg)[lane];
    for (int j = warp; j < 40; j += 4) {
        float4 xv = ((const float4*)g_fs)[(size_t)(b * 40 + j) * 32 + lane];
        float p = xv.x * wg.x + xv.y * wg.y + xv.z * wg.z + xv.w * wg.w;
#pragma unroll
        for (int off = 16; off; off >>= 1) p += __shfl_xor_sync(0xffffffffu, p, off);
        if (lane == 0) gate[j] = p + bg[0];
    }
    __syncthreads();
    if (tid == 0) {
        float m = gate[0];
        for (int j = 1; j < 40; j++) m = fmaxf(m, gate[j]);
        float s = 0.f;
        for (int j = 0; j < 40; j++) s += __expf(gate[j] - m);
        ms[0] = m; ms[1] = s;
    }
    __syncthreads();
    if (tid < 40) alpha[tid] = __expf(gate[tid] - ms[0]) / (ms[1] + 1e-16f);
    __syncthreads();
    float acc = 0.f;
    for (int j = 0; j < 40; j++)
        acc += alpha[j] * g_fs[(size_t)(b * 40 + j) * E_ + tid];
    g_fn[(size_t)b * E_ + tid] = acc;
}

// ---------------- cosine ----------------
__global__ void cos_kernel(float* __restrict__ out) {
    int warp = threadIdx.x >> 5, lane = threadIdx.x & 31;
    int b = blockIdx.x * 8 + warp;
    float4 a4 = ((const float4*)g_fn)[(size_t)b * 32 + lane];
    float4 b4 = ((const float4*)g_hn)[(size_t)b * 32 + lane];
    float dt = a4.x * b4.x + a4.y * b4.y + a4.z * b4.z + a4.w * b4.w;
    float na = a4.x * a4.x + a4.y * a4.y + a4.z * a4.z + a4.w * a4.w;
    float nb = b4.x * b4.x + b4.y * b4.y + b4.z * b4.z + b4.w * b4.w;
#pragma unroll
    for (int off = 16; off; off >>= 1) {
        dt += __shfl_xor_sync(0xffffffffu, dt, off);
        na += __shfl_xor_sync(0xffffffffu, na, off);
        nb += __shfl_xor_sync(0xffffffffu, nb, off);
    }
    if (lane == 0)
        out[b] = dt / (fmaxf(sqrtf(na), 1e-8f) * fmaxf(sqrtf(nb), 1e-8f));
}

// ---------------- launch (stream DAG inside graph capture) ----------------
extern "C" void kernel_launch(void* const* d_in, const int* in_sizes, int n_in,
                              void* d_out, int out_size) {
    const int* desc_tokens = (const int*)d_in[0];
    const int* x_tokens    = (const int*)d_in[1];
    const int* mini_tokens = (const int*)d_in[2];
    const int* src         = (const int*)d_in[3];
    const int* dst         = (const int*)d_in[4];
    const int* mini_src    = (const int*)d_in[5];
    const int* mini_dst    = (const int*)d_in[6];
    const float* desc_table  = (const float*)d_in[9];
    const float* code_table  = (const float*)d_in[10];
    const float* code_table2 = (const float*)d_in[11];
    const float* Wq = (const float*)d_in[12]; const float* bq = (const float*)d_in[13];
    const float* Wk = (const float*)d_in[14]; const float* bk = (const float*)d_in[15];
    const float* Wv = (const float*)d_in[16]; const float* bv = (const float*)d_in[17];
    const float* Wskip = (const float*)d_in[18]; const float* bskip = (const float*)d_in[19];
    const float* W2 = (const float*)d_in[20]; const float* b2 = (const float*)d_in[21];
    const float* W3 = (const float*)d_in[22]; const float* b3 = (const float*)d_in[23];
    const float* Wg = (const float*)d_in[24]; const float* bg = (const float*)d_in[25];
    float* out = (float*)d_out;

    float *p_q, *p_k, *p_v, *p_hidden, *p_hn, *p_stmt, *p_xw1, *p_xw2, *p_fs;
    cudaGetSymbolAddress((void**)&p_q, g_q);
    cudaGetSymbolAddress((void**)&p_k, g_k);
    cudaGetSymbolAddress((void**)&p_v, g_v);
    cudaGetSymbolAddress((void**)&p_hidden, g_hidden);
    cudaGetSymbolAddress((void**)&p_hn, g_hn);
    cudaGetSymbolAddress((void**)&p_stmt, g_stmt);
    cudaGetSymbolAddress((void**)&p_xw1, g_xw1);
    cudaGetSymbolAddress((void**)&p_xw2, g_xw2);
    cudaGetSymbolAddress((void**)&p_fs, g_fs);

    __nv_bfloat16 *p_mini_hi, *p_mini_lo, *p_mfn_hi, *p_mfn_lo, *p_gc1_hi, *p_gc1_lo;
    __nv_bfloat16 *p_w2t_hi, *p_w2t_lo, *p_w3t_hi, *p_w3t_lo;
    cudaGetSymbolAddress((void**)&p_mini_hi, g_mini_hi);
    cudaGetSymbolAddress((void**)&p_mini_lo, g_mini_lo);
    cudaGetSymbolAddress((void**)&p_mfn_hi, g_mfn_hi);
    cudaGetSymbolAddress((void**)&p_mfn_lo, g_mfn_lo);
    cudaGetSymbolAddress((void**)&p_gc1_hi, g_gc1_hi);
    cudaGetSymbolAddress((void**)&p_gc1_lo, g_gc1_lo);
    cudaGetSymbolAddress((void**)&p_w2t_hi, g_w2t_hi);
    cudaGetSymbolAddress((void**)&p_w2t_lo, g_w2t_lo);
    cudaGetSymbolAddress((void**)&p_w3t_hi, g_w3t_hi);
    cudaGetSymbolAddress((void**)&p_w3t_lo, g_w3t_lo);

    int *p_deg_m, *p_off_m, *p_pos_m, *p_csr_m, *p_bsum_m;
    int *p_deg_o, *p_off_o, *p_pos_o, *p_csr_o, *p_bsum_o;
    cudaGetSymbolAddress((void**)&p_deg_m, g_deg_m);
    cudaGetSymbolAddress((void**)&p_off_m, g_off_m);
    cudaGetSymbolAddress((void**)&p_pos_m, g_pos_m);
    cudaGetSymbolAddress((void**)&p_csr_m, g_csr_m);
    cudaGetSymbolAddress((void**)&p_bsum_m, g_bsum_m);
    cudaGetSymbolAddress((void**)&p_deg_o, g_deg_o);
    cudaGetSymbolAddress((void**)&p_off_o, g_off_o);
    cudaGetSymbolAddress((void**)&p_pos_o, g_pos_o);
    cudaGetSymbolAddress((void**)&p_csr_o, g_csr_o);
    cudaGetSymbolAddress((void**)&p_bsum_o, g_bsum_o);

    cudaFuncSetAttribute(bf16_gemm_qkvs, cudaFuncAttributeMaxDynamicSharedMemorySize, GEMM_SMEM);
    cudaFuncSetAttribute(bf16_gemm, cudaFuncAttributeMaxDynamicSharedMemorySize, GEMM_SMEM);

    // one-time stream/event resources (resource init only; identical work every call)
    static cudaStream_t s1 = nullptr, s2 = nullptr;
    static cudaEvent_t e_root = nullptr, e_csrm = nullptr, e_csro = nullptr,
                       e_ws = nullptr, e_emb2 = nullptr;
    if (!s1) {
        cudaStreamCreateWithFlags(&s1, cudaStreamNonBlocking);
        cudaStreamCreateWithFlags(&s2, cudaStreamNonBlocking);
        cudaEventCreateWithFlags(&e_root, cudaEventDisableTiming);
        cudaEventCreateWithFlags(&e_csrm, cudaEventDisableTiming);
        cudaEventCreateWithFlags(&e_csro, cudaEventDisableTiming);
        cudaEventCreateWithFlags(&e_ws, cudaEventDisableTiming);
        cudaEventCreateWithFlags(&e_emb2, cudaEventDisableTiming);
    }

    // fork side streams from the capture (default) stream
    cudaEventRecord(e_root, 0);
    cudaStreamWaitEvent(s1, e_root, 0);
    cudaStreamWaitEvent(s2, e_root, 0);

    // ---- s1: CSR builds ----
    zero_deg_kernel<<<(NM_ + 255) / 256, 256, 0, s1>>>();
    count_kernel<<<(EM_ + 255) / 256, 256, 0, s1>>>(mini_dst, p_deg_m, EM_);
    count_kernel<<<(EO_ + 255) / 256, 256, 0, s1>>>(dst, p_deg_o, EO_);
    scan_local_kernel<<<NM_ / 1024, 256, 0, s1>>>(p_deg_m, p_off_m, p_bsum_m);
    scan_bsums_kernel<<<1, 128, 0, s1>>>(p_bsum_m, NM_ / 1024, p_off_m, NM_);
    scan_add_kernel<<<NM_ / 256, 256, 0, s1>>>(p_off_m, p_pos_m, p_bsum_m, NM_);
    scatter_kernel<<<(EM_ + 255) / 256, 256, 0, s1>>>(mini_src, mini_dst, p_pos_m, p_csr_m, EM_);
    cudaEventRecord(e_csrm, s1);
    scan_local_kernel<<<NO_ / 1024, 256, 0, s1>>>(p_deg_o, p_off_o, p_bsum_o);
    scan_bsums_kernel<<<1, 128, 0, s1>>>(p_bsum_o, NO_ / 1024, p_off_o, NO_);
    scan_add_kernel<<<NO_ / 256, 256, 0, s1>>>(p_off_o, p_pos_o, p_bsum_o, NO_);
    dinv_kernel<<<(NO_ + 255) / 256, 256, 0, s1>>>();
    scatter_kernel<<<(EO_ + 255) / 256, 256, 0, s1>>>(src, dst, p_pos_o, p_csr_o, EO_);
    cudaEventRecord(e_csro, s1);

    // ---- s2: weight splits + secondary embeddings ----
    {
        dim3 g((E_ * E_ + 255) / 256, 4);
        wsplit4_kernel<<<g, 256, 0, s2>>>(Wq, Wk, Wv, Wskip);
    }
    wsplit_kernel<<<(E_ * HID_ + 255) / 256, 256, 0, s2>>>(W2, p_w2t_hi, p_w2t_lo, E_, HID_);
    wsplit_kernel<<<(HID_ * E_ + 255) / 256, 256, 0, s2>>>(W3, p_w3t_hi, p_w3t_lo, HID_, E_);
    cudaEventRecord(e_ws, s2);
    masked_mean4_kernel<<<NO_ / 4, 128, 0, s2>>>(x_tokens, code_table2, p_stmt, LO_);
    masked_mean4_kernel<<<B_ / 4, 128, 0, s2>>>(desc_tokens, desc_table, p_hn, LD_);
    cudaEventRecord(e_emb2, s2);

    // ---- main stream: critical path ----
    masked_mean4_bf16_kernel<<<NM_ / 4, 128>>>(mini_tokens, code_table, p_mini_hi, p_mini_lo, LM_);

    cudaStreamWaitEvent(0, e_ws, 0);
    {
        dim3 grid(NM_ / 128, 4);
        bf16_gemm_qkvs<<<grid, 256, GEMM_SMEM>>>(p_mini_hi, p_mini_lo,
                                                 bq, p_q, bk, p_k, bv, p_v, bskip, p_hidden);
    }

    cudaStreamWaitEvent(0, e_csrm, 0);
    attn_kernel<<<NM_ / 8, 256>>>();

    cudaStreamWaitEvent(0, e_emb2, 0);
    gattn8_kernel<<<NO_ / 8, 256>>>(Wg, bg);

    {
        dim3 grid(NO_ / 128, HID_ / 128);
        bf16_gemm<<<grid, 256, GEMM_SMEM>>>(p_mfn_hi, p_mfn_lo, p_w2t_hi, p_w2t_lo,
                                            p_xw1, E_, HID_);
    }
    cudaStreamWaitEvent(0, e_csro, 0);
    gcn_gather_split_kernel<<<NO_ / 8, 256>>>(p_xw1, b2, p_gc1_hi, p_gc1_lo, HID_ / 4);

    {
        dim3 grid(NO_ / 128, E_ / 128);
        bf16_gemm<<<grid, 256, GEMM_SMEM>>>(p_gc1_hi, p_gc1_lo, p_w3t_hi, p_w3t_lo,
                                            p_xw2, HID_, E_);
    }
    gcn_gather_kernel<<<NO_ / 8, 256>>>(p_xw2, b3, p_fs, E_ / 4);

    gattn40_kernel<<<B_, E_>>>(Wg, bg);
    cos_kernel<<<B_ / 8, 256>>>(out);
    (void)in_sizes; (void)n_in; (void)out_size;
}